// round 10
// baseline (speedup 1.0000x reference)
#include <cuda_runtime.h>
#include <cuda_bf16.h>
#include <mma.h>
#include <cstdint>

using namespace nvcuda;

#define NB   4
#define CIN  512
#define COUT 64
#define SS   16384   // T*H*W
#define NSPLIT 32
#define MTOT 640     // 512 (add1) + 128 (occ1) fused rows

// ---------------- scratch (device globals; no allocs allowed) ----------------
__device__ float g_y1  [(size_t)NB * CIN * SS];   // relu(add1) fp32 (B,512,S)
__device__ float g_h1  [(size_t)NB * 128 * SS];   // relu(occ1)
__device__ float g_occ [(size_t)NB *  64 * SS];
__device__ float g_P   [(size_t)NB * COUT * CIN];
__device__ float g_q   [(size_t)NB * COUT];
__device__ __nv_bfloat16 g_wch[MTOT * CIN];       // concat W rows, hi
__device__ __nv_bfloat16 g_wcl[MTOT * CIN];       // concat W rows, lo
__device__ float g_bc[MTOT];                      // concat bias

// ---------------- helpers ----------------------------------------------------
__device__ __forceinline__ uint32_t smem_u32(const void* p) {
    uint32_t a;
    asm("{ .reg .u64 t; cvta.to.shared.u64 t, %1; cvt.u32.u64 %0, t; }" : "=r"(a) : "l"(p));
    return a;
}
__device__ __forceinline__ void cp16(uint32_t dst, const void* src) {
    asm volatile("cp.async.cg.shared.global [%0], [%1], 16;" :: "r"(dst), "l"(src));
}
__device__ __forceinline__ void cp_commit() {
    asm volatile("cp.async.commit_group;" ::: "memory");
}
template<int N>
__device__ __forceinline__ void cp_wait() {
    asm volatile("cp.async.wait_group %0;" :: "n"(N) : "memory");
}

// ---------------- pre-passes (3 launches so hmma_gemm is launch #4) ----------
__global__ void wsplit_all(const float* __restrict__ W1, const float* __restrict__ Wo1,
                           __nv_bfloat16* __restrict__ H, __nv_bfloat16* __restrict__ L)
{
    int i = blockIdx.x * 256 + threadIdx.x;
    if (i >= MTOT * CIN) return;
    float v = (i < 512 * CIN) ? W1[i] : Wo1[i - 512 * CIN];
    __nv_bfloat16 h = __float2bfloat16(v);
    H[i] = h;
    L[i] = __float2bfloat16(v - __bfloat162float(h));
}

__global__ void prep_bias(const float* __restrict__ b1, const float* __restrict__ bo1,
                          float* __restrict__ bc, float* __restrict__ q)
{
    int i = blockIdx.x * 256 + threadIdx.x;
    if (i < NB * COUT) q[i] = 0.f;
    if (i < 512) bc[i] = b1[i];
    else if (i < MTOT) bc[i] = bo1[i - 512];
}

__global__ void zero_P(float* __restrict__ P)
{
    int i = blockIdx.x * 256 + threadIdx.x;
    if (i < NB * COUT * CIN) P[i] = 0.f;
}

// ---------------- merged HMMA GEMM, B built in-regs from native-layout x -----
// D(128x128) = Wc(640,512) x X(512,S) tile. A = W bf16 hi/lo rows (cp.async).
// B: fp32 X loaded to REGS (coalesced, row-major k x n), hi/lo split in regs,
// stored row-major to smem (wmma matrix_b row_major). No transpose anywhere.
// 3-term: Ahi*Bhi + Ahi*Blo + Alo*Bhi (fp32 accum). bias+relu epilogue,
// rows m0<512 -> y1 (B,512,S); rows m0>=512 -> h1 (B,128,S).
//
// smem per stage: Ahi 10240 | Alo 10240 | Bhi 8704 (32x136 bf16) | Blo 8704
#define STAGE_B 37888
#define A_LO    10240
#define B_HI    20480
#define B_LO    29184
#define HSMEM   75776
__global__ __launch_bounds__(256)
void hmma_gemm(const __nv_bfloat16* __restrict__ Wh, const __nv_bfloat16* __restrict__ Wl,
               const float* __restrict__ X, const float* __restrict__ bias,
               float* __restrict__ Y1, float* __restrict__ H1)
{
    extern __shared__ __align__(128) char smem[];
    const int t = threadIdx.x, wid = t >> 5;
    const int n0 = blockIdx.x * 128, m0 = blockIdx.y * 128, b = blockIdx.z;
    const uint32_t sb = smem_u32(smem);

    const int wm = wid & 3;        // 4 warp rows -> 32 m each
    const int wn = wid >> 2;       // 2 warp cols -> 64 n each

    const __nv_bfloat16* wh = Wh + (long)m0 * 512;
    const __nv_bfloat16* wl = Wl + (long)m0 * 512;
    const float*         xb = X + (long)b * CIN * SS + n0;

    // per-thread X mapping: k-row = t>>3 (0..31), n-seg = (t&7)*16
    const int kq   = t >> 3;
    const int nseg = (t & 7) * 16;

    auto cpA = [&](int c, int st) {
        const int k0 = c * 32;
#pragma unroll
        for (int i = 0; i < 4; ++i) {
            const int vid = t + i * 256;
            const int tile = vid >> 9;           // 0 = hi, 1 = lo
            const int r    = (vid >> 2) & 127;
            const int v    = vid & 3;
            cp16(sb + st * STAGE_B + tile * A_LO + r * 80 + v * 16,
                 (tile == 0 ? wh : wl) + (long)r * 512 + k0 + v * 8);
        }
        cp_commit();
    };

    float4 xv[4];
    auto ldgX = [&](int c) {
        const float* src = xb + (long)(c * 32 + kq) * SS + nseg;
        xv[0] = *(const float4*)(src + 0);
        xv[1] = *(const float4*)(src + 4);
        xv[2] = *(const float4*)(src + 8);
        xv[3] = *(const float4*)(src + 12);
    };
    auto convert = [&](int st) {
        __nv_bfloat16* Bh = (__nv_bfloat16*)(smem + st * STAGE_B + B_HI) + kq * 136 + nseg;
        __nv_bfloat16* Bl = (__nv_bfloat16*)(smem + st * STAGE_B + B_LO) + kq * 136 + nseg;
        union U8 { uint4 u[2]; __nv_bfloat16 h[16]; } uh, ul;
        const float* xf = (const float*)xv;
#pragma unroll
        for (int q = 0; q < 16; ++q) {
            float v = xf[q];
            __nv_bfloat16 h = __float2bfloat16(v);
            uh.h[q] = h;
            ul.h[q] = __float2bfloat16(v - __bfloat162float(h));
        }
        *(uint4*)(Bh + 0) = uh.u[0];
        *(uint4*)(Bh + 8) = uh.u[1];
        *(uint4*)(Bl + 0) = ul.u[0];
        *(uint4*)(Bl + 8) = ul.u[1];
    };

    wmma::fragment<wmma::accumulator, 16, 16, 16, float> acc[2][4];
#pragma unroll
    for (int i = 0; i < 2; ++i)
#pragma unroll
        for (int j = 0; j < 4; ++j) wmma::fill_fragment(acc[i][j], 0.0f);

    // prologue
    ldgX(0);
    cpA(0, 0);

    for (int c = 0; c < 16; ++c) {
        const int st = c & 1, nx = st ^ 1;
        cp_wait<0>();              // A(c) landed (this thread's group)
        convert(st);               // B(st) from regs (chunk c)
        if (c + 1 < 16) { ldgX(c + 1); cpA(c + 1, nx); }   // overlap with MMA
        __syncthreads();           // A(st)+B(st) visible to all

        const __nv_bfloat16* Ah  = (const __nv_bfloat16*)(smem + st * STAGE_B);
        const __nv_bfloat16* Al  = (const __nv_bfloat16*)(smem + st * STAGE_B + A_LO);
        const __nv_bfloat16* Bhs = (const __nv_bfloat16*)(smem + st * STAGE_B + B_HI);
        const __nv_bfloat16* Bls = (const __nv_bfloat16*)(smem + st * STAGE_B + B_LO);

#pragma unroll
        for (int kk = 0; kk < 32; kk += 16) {
            wmma::fragment<wmma::matrix_a, 16, 16, 16, __nv_bfloat16, wmma::row_major> fah[2], fal[2];
#pragma unroll
            for (int i = 0; i < 2; ++i) {
                wmma::load_matrix_sync(fah[i], Ah + (wm * 32 + i * 16) * 40 + kk, 40);
                wmma::load_matrix_sync(fal[i], Al + (wm * 32 + i * 16) * 40 + kk, 40);
            }
#pragma unroll
            for (int j = 0; j < 4; ++j) {
                wmma::fragment<wmma::matrix_b, 16, 16, 16, __nv_bfloat16, wmma::row_major> fbh, fbl;
                wmma::load_matrix_sync(fbh, Bhs + kk * 136 + wn * 64 + j * 16, 136);
                wmma::load_matrix_sync(fbl, Bls + kk * 136 + wn * 64 + j * 16, 136);
#pragma unroll
                for (int i = 0; i < 2; ++i) {
                    wmma::mma_sync(acc[i][j], fah[i], fbh, acc[i][j]);
                    wmma::mma_sync(acc[i][j], fah[i], fbl, acc[i][j]);
                    wmma::mma_sync(acc[i][j], fal[i], fbh, acc[i][j]);
                }
            }
        }
        __syncthreads();           // stage-st reads done before next writes
    }

    // ---- epilogue: bias + relu, routed ----
    float* Dsm = (float*)smem;    // [m][n] 128 x 132
#pragma unroll
    for (int i = 0; i < 2; ++i)
#pragma unroll
        for (int j = 0; j < 4; ++j)
            wmma::store_matrix_sync(Dsm + (wm * 32 + i * 16) * 132 + wn * 64 + j * 16,
                                    acc[i][j], 132, wmma::mem_row_major);
    __syncthreads();
    const int r  = t >> 1;
    const int cb = (t & 1) * 64;
    const float bv = bias[m0 + r];
    float* yr = (m0 < 512)
              ? Y1 + ((long)b * CIN + m0 + r) * SS + n0 + cb
              : H1 + ((long)b * 128 + (m0 - 512) + r) * SS + n0 + cb;
#pragma unroll
    for (int j = 0; j < 64; j += 4) {
        float4 v;
        v.x = fmaxf(Dsm[r * 132 + cb + j + 0] + bv, 0.f);
        v.y = fmaxf(Dsm[r * 132 + cb + j + 1] + bv, 0.f);
        v.z = fmaxf(Dsm[r * 132 + cb + j + 2] + bv, 0.f);
        v.w = fmaxf(Dsm[r * 132 + cb + j + 3] + bv, 0.f);
        *(float4*)(yr + j) = v;
    }
}

// -------- fused occ tail: h2 = relu(Wo2 h1 + b), occ = |Wo3 h2|, q += sums ----
#define W2OFF 0
#define W3OFF 33792
#define H1OFF 51200
#define H2OFF 68096
#define OSMEM 101888
__global__ __launch_bounds__(256)
void occ_tail(const float* __restrict__ h1, const float* __restrict__ wo2,
              const float* __restrict__ bo2, const float* __restrict__ wo3,
              float* __restrict__ occ, float* __restrict__ q)
{
    extern __shared__ __align__(16) char smem[];
    float* W2s = (float*)(smem + W2OFF);   // [64][132]
    float* W3s = (float*)(smem + W3OFF);   // [64][68]
    float* H1s = (float*)(smem + H1OFF);   // [32][132]
    float* H2s = (float*)(smem + H2OFF);   // [64][132]

    const int t = threadIdx.x;
    const int s0 = blockIdx.x * 128, b = blockIdx.z;
    const int tm = t >> 4, tn = t & 15;    // 16 x 16

#pragma unroll
    for (int i = 0; i < 8; ++i) {
        const int vid = t + i * 256;
        const int r = vid >> 5, c4 = (vid & 31) * 4;
        *(float4*)&W2s[r * 132 + c4] = *(const float4*)(wo2 + r * 128 + c4);
    }
#pragma unroll
    for (int i = 0; i < 4; ++i) {
        const int vid = t + i * 256;
        const int r = vid >> 4, c4 = (vid & 15) * 4;
        *(float4*)&W3s[r * 68 + c4] = *(const float4*)(wo3 + r * 64 + c4);
    }

    float acc1[4][8];
#pragma unroll
    for (int i = 0; i < 4; ++i)
#pragma unroll
        for (int j = 0; j < 8; ++j) acc1[i][j] = 0.f;

    for (int c0 = 0; c0 < 128; c0 += 32) {
        __syncthreads();
#pragma unroll
        for (int i = 0; i < 4; ++i) {
            const int vid = t + i * 256;
            const int r = vid >> 5, sc = (vid & 31) * 4;
            *(float4*)&H1s[r * 132 + sc] =
                *(const float4*)(h1 + ((long)b * 128 + c0 + r) * SS + s0 + sc);
        }
        __syncthreads();
#pragma unroll
        for (int kk = 0; kk < 32; ++kk) {
            float a[4], v[8];
#pragma unroll
            for (int i = 0; i < 4; ++i) a[i] = W2s[(tm * 4 + i) * 132 + c0 + kk];
#pragma unroll
            for (int j = 0; j < 8; ++j) v[j] = H1s[kk * 132 + tn * 8 + j];
#pragma unroll
            for (int i = 0; i < 4; ++i)
#pragma unroll
                for (int j = 0; j < 8; ++j) acc1[i][j] += a[i] * v[j];
        }
    }
    __syncthreads();
#pragma unroll
    for (int i = 0; i < 4; ++i) {
        const float bv = bo2[tm * 4 + i];
#pragma unroll
        for (int j = 0; j < 8; ++j)
            H2s[(tm * 4 + i) * 132 + tn * 8 + j] = fmaxf(acc1[i][j] + bv, 0.f);
    }
    __syncthreads();

    float acc2[4][8];
#pragma unroll
    for (int i = 0; i < 4; ++i)
#pragma unroll
        for (int j = 0; j < 8; ++j) acc2[i][j] = 0.f;
#pragma unroll
    for (int kk = 0; kk < 64; ++kk) {
        float a[4], v[8];
#pragma unroll
        for (int i = 0; i < 4; ++i) a[i] = W3s[(tm * 4 + i) * 68 + kk];
#pragma unroll
        for (int j = 0; j < 8; ++j) v[j] = H2s[kk * 132 + tn * 8 + j];
#pragma unroll
        for (int i = 0; i < 4; ++i)
#pragma unroll
            for (int j = 0; j < 8; ++j) acc2[i][j] += a[i] * v[j];
    }
#pragma unroll
    for (int i = 0; i < 4; ++i) {
        const int o = tm * 4 + i;
        float4 v0, v1;
        float* dst = occ + ((long)b * COUT + o) * SS + s0 + tn * 8;
        v0.x = fabsf(acc2[i][0]); v0.y = fabsf(acc2[i][1]);
        v0.z = fabsf(acc2[i][2]); v0.w = fabsf(acc2[i][3]);
        v1.x = fabsf(acc2[i][4]); v1.y = fabsf(acc2[i][5]);
        v1.z = fabsf(acc2[i][6]); v1.w = fabsf(acc2[i][7]);
        *(float4*)dst = v0;
        *(float4*)(dst + 4) = v1;
        float qp = v0.x + v0.y + v0.z + v0.w + v1.x + v1.y + v1.z + v1.w;
#pragma unroll
        for (int off = 8; off > 0; off >>= 1)
            qp += __shfl_xor_sync(0xffffffff, qp, off);
        if (tn == 0) atomicAdd(&q[b * COUT + o], qp * (1.0f / (float)SS));
    }
}

// ------ P[b,o,k] = (1/S) sum_s occ[b,o,s] * y1[b,k,s]  (split-K atomics) ------
__global__ __launch_bounds__(256)
void pool_contract(const float* __restrict__ Occ, const float* __restrict__ Y1,
                   float* __restrict__ P)
{
    const int S = SS;
    const int bz = blockIdx.z;
    const int b  = bz / NSPLIT;
    const int sp = bz % NSPLIT;
    const int chunk = S / NSPLIT;
    const int sbeg  = sp * chunk;

    const float* Ab = Occ + (long)b * COUT * S;
    const float* Fb = Y1  + (long)b * CIN  * S;
    const int n0 = blockIdx.x * 64;

    __shared__ float As[16][64 + 4];
    __shared__ float Bs[16][64 + 4];

    const int t  = threadIdx.x;
    const int tn = t % 16;
    const int tm = t / 16;
    const int lrow = t >> 2;
    const int lk   = (t & 3) * 4;

    float acc[4][4];
#pragma unroll
    for (int i = 0; i < 4; i++)
#pragma unroll
        for (int j = 0; j < 4; j++) acc[i][j] = 0.f;

    for (int s0 = sbeg; s0 < sbeg + chunk; s0 += 16) {
        float4 a4 = *(const float4*)(Ab + (long)lrow * S + s0 + lk);
        As[lk+0][lrow] = a4.x; As[lk+1][lrow] = a4.y;
        As[lk+2][lrow] = a4.z; As[lk+3][lrow] = a4.w;
        float4 f4 = *(const float4*)(Fb + (long)(n0 + lrow) * S + s0 + lk);
        Bs[lk+0][lrow] = f4.x; Bs[lk+1][lrow] = f4.y;
        Bs[lk+2][lrow] = f4.z; Bs[lk+3][lrow] = f4.w;
        __syncthreads();

#pragma unroll
        for (int kk = 0; kk < 16; kk++) {
            float4 av = *(const float4*)&As[kk][tm * 4];
            float4 bv = *(const float4*)&Bs[kk][tn * 4];
            float a[4] = {av.x, av.y, av.z, av.w};
            float c[4] = {bv.x, bv.y, bv.z, bv.w};
#pragma unroll
            for (int i = 0; i < 4; i++)
#pragma unroll
                for (int j = 0; j < 4; j++) acc[i][j] += a[i] * c[j];
        }
        __syncthreads();
    }

    const float scale = 1.0f / (float)S;
#pragma unroll
    for (int i = 0; i < 4; i++)
#pragma unroll
        for (int j = 0; j < 4; j++) {
            const int o = tm * 4 + i;
            const int k = n0 + tn * 4 + j;
            atomicAdd(&P[((long)b * COUT + o) * CIN + k], acc[i][j] * scale);
        }
}

// ------ out[b,o,c] = sum_k P[b,o,k]*W2[c,k] + q[b,o]*b2[c] -------------------
__global__ __launch_bounds__(256)
void fin_gemm(const float* __restrict__ P, const float* __restrict__ q,
              const float* __restrict__ W2, const float* __restrict__ b2,
              float* __restrict__ out)
{
    const int b = blockIdx.z, c0 = blockIdx.x * 64;
    __shared__ float Pt[64][68];
    __shared__ float Wt[64][68];
    const int t = threadIdx.x;
    const int tm = t >> 4, tn = t & 15;

    float acc[4][4];
#pragma unroll
    for (int i = 0; i < 4; i++)
#pragma unroll
        for (int j = 0; j < 4; j++) acc[i][j] = 0.f;

    for (int k0 = 0; k0 < CIN; k0 += 64) {
#pragma unroll
        for (int i = 0; i < 4; ++i) {
            const int r  = (t >> 4) + i * 16;
            const int kc = (t & 15) * 4;
            *(float4*)&Pt[r][kc] = *(const float4*)(P + ((long)b * COUT + r) * CIN + k0 + kc);
            *(float4*)&Wt[r][kc] = *(const float4*)(W2 + (long)(c0 + r) * CIN + k0 + kc);
        }
        __syncthreads();
#pragma unroll
        for (int kk = 0; kk < 64; ++kk) {
            float a[4], w[4];
#pragma unroll
            for (int i = 0; i < 4; ++i) a[i] = Pt[tm * 4 + i][kk];
#pragma unroll
            for (int j = 0; j < 4; ++j) w[j] = Wt[tn * 4 + j][kk];
#pragma unroll
            for (int i = 0; i < 4; ++i)
#pragma unroll
                for (int j = 0; j < 4; ++j) acc[i][j] += a[i] * w[j];
        }
        __syncthreads();
    }

#pragma unroll
    for (int i = 0; i < 4; ++i) {
        const int o = tm * 4 + i;
        const float qv = q[b * COUT + o];
#pragma unroll
        for (int j = 0; j < 4; ++j) {
            const int c = c0 + tn * 4 + j;
            out[((long)b * COUT + o) * CIN + c] = acc[i][j] + qv * b2[c];
        }
    }
}

// -----------------------------------------------------------------------------
extern "C" void kernel_launch(void* const* d_in, const int* in_sizes, int n_in,
                              void* d_out, int out_size)
{
    const float* x      = (const float*)d_in[0];
    const float* w_add1 = (const float*)d_in[1];
    const float* b_add1 = (const float*)d_in[2];
    const float* w_add2 = (const float*)d_in[3];
    const float* b_add2 = (const float*)d_in[4];
    const float* w_occ1 = (const float*)d_in[5];
    const float* b_occ1 = (const float*)d_in[6];
    const float* w_occ2 = (const float*)d_in[7];
    const float* b_occ2 = (const float*)d_in[8];
    const float* w_occ3 = (const float*)d_in[9];
    float* out = (float*)d_out;

    __nv_bfloat16 *wch, *wcl;
    float *y1, *h1, *occ, *P, *q, *bc;
    cudaGetSymbolAddress((void**)&y1,  g_y1);
    cudaGetSymbolAddress((void**)&h1,  g_h1);
    cudaGetSymbolAddress((void**)&occ, g_occ);
    cudaGetSymbolAddress((void**)&P,   g_P);
    cudaGetSymbolAddress((void**)&q,   g_q);
    cudaGetSymbolAddress((void**)&wch, g_wch);
    cudaGetSymbolAddress((void**)&wcl, g_wcl);
    cudaGetSymbolAddress((void**)&bc,  g_bc);

    cudaFuncSetAttribute(hmma_gemm, cudaFuncAttributeMaxDynamicSharedMemorySize, HSMEM);
    cudaFuncSetAttribute(occ_tail,  cudaFuncAttributeMaxDynamicSharedMemorySize, OSMEM);

    // launches #1-#3 (pre), #4 = hmma_gemm (ncu captures launch #4)
    wsplit_all<<<(MTOT*CIN + 255) / 256, 256>>>(w_add1, w_occ1, wch, wcl);
    prep_bias<<<(MTOT + 255) / 256, 256>>>(b_add1, b_occ1, bc, q);
    zero_P<<<(NB*COUT*CIN + 255) / 256, 256>>>(P);

    // merged add1 + occ1 (x consumed directly, no transpose pre-pass)
    hmma_gemm<<<dim3(SS/128, MTOT/128, NB), 256, HSMEM>>>(wch, wcl, x, bc, y1, h1);

    // fused occ tail (occ2 + occ3 + q)
    occ_tail<<<dim3(SS/128, 1, NB), 256, OSMEM>>>(h1, w_occ2, b_occ2, w_occ3, occ, q);

    // P = (1/S) occ . y1^T
    pool_contract<<<dim3(CIN/64, 1, NB * NSPLIT), 256>>>(occ, y1, P);

    // out = P . W2^T + q b2^T
    fin_gemm<<<dim3(CIN/64, 1, NB), 256>>>(P, q, w_add2, b_add2, out);
}

// round 11
// speedup vs baseline: 1.1572x; 1.1572x over previous
#include <cuda_runtime.h>
#include <cuda_bf16.h>
#include <mma.h>
#include <cstdint>

using namespace nvcuda;

#define NB   4
#define CIN  512
#define COUT 64
#define SS   16384   // T*H*W
#define NSPLIT 32
#define MTOT 640     // 512 (add1) + 128 (occ1) fused rows

// ---------------- scratch (device globals; no allocs allowed) ----------------
__device__ __nv_bfloat16 g_xt_hi[(size_t)NB * SS * CIN];
__device__ __nv_bfloat16 g_xt_lo[(size_t)NB * SS * CIN];
__device__ float g_y1  [(size_t)NB * CIN * SS];   // relu(add1) fp32 (B,512,S)
__device__ float g_h1  [(size_t)NB * 128 * SS];   // relu(occ1)
__device__ float g_occ [(size_t)NB *  64 * SS];
__device__ float g_P   [(size_t)NB * COUT * CIN];
__device__ float g_q   [(size_t)NB * COUT];
__device__ __nv_bfloat16 g_wch[MTOT * CIN];       // concat W rows, hi
__device__ __nv_bfloat16 g_wcl[MTOT * CIN];       // concat W rows, lo
__device__ float g_bc[MTOT];                      // concat bias

// ---------------- helpers ----------------------------------------------------
__device__ __forceinline__ uint32_t smem_u32(const void* p) {
    uint32_t a;
    asm("{ .reg .u64 t; cvta.to.shared.u64 t, %1; cvt.u32.u64 %0, t; }" : "=r"(a) : "l"(p));
    return a;
}
__device__ __forceinline__ void cp16(uint32_t dst, const void* src) {
    asm volatile("cp.async.cg.shared.global [%0], [%1], 16;" :: "r"(dst), "l"(src));
}
__device__ __forceinline__ void cp_commit() {
    asm volatile("cp.async.commit_group;" ::: "memory");
}
template<int N>
__device__ __forceinline__ void cp_wait() {
    asm volatile("cp.async.wait_group %0;" :: "n"(N) : "memory");
}

// ---------------- pre-passes (3 launches so hmma_gemm is launch #4) ----------
__global__ __launch_bounds__(256)
void transpose_split(const float* __restrict__ X,
                     __nv_bfloat16* __restrict__ H, __nv_bfloat16* __restrict__ L)
{
    __shared__ float tile[32][33];
    const int s0 = blockIdx.x * 32, c0 = blockIdx.y * 32, b = blockIdx.z;
    const int tx = threadIdx.x, ty = threadIdx.y;   // 32 x 8
    const float* Xb = X + ((long)b * CIN + c0) * SS + s0;
#pragma unroll
    for (int j = 0; j < 4; ++j)
        tile[ty + 8 * j][tx] = Xb[(long)(ty + 8 * j) * SS + tx];
    __syncthreads();
#pragma unroll
    for (int j = 0; j < 4; ++j) {
        const int s = ty + 8 * j;
        float v = tile[tx][s];
        const long off = ((long)b * SS + s0 + s) * CIN + c0 + tx;
        __nv_bfloat16 hi = __float2bfloat16(v);
        H[off] = hi;
        L[off] = __float2bfloat16(v - __bfloat162float(hi));
    }
}

__global__ void wsplit_all(const float* __restrict__ W1, const float* __restrict__ Wo1,
                           __nv_bfloat16* __restrict__ H, __nv_bfloat16* __restrict__ L)
{
    int i = blockIdx.x * 256 + threadIdx.x;
    if (i >= MTOT * CIN) return;
    float v = (i < 512 * CIN) ? W1[i] : Wo1[i - 512 * CIN];
    __nv_bfloat16 h = __float2bfloat16(v);
    H[i] = h;
    L[i] = __float2bfloat16(v - __bfloat162float(h));
}

__global__ void prep(const float* __restrict__ b1, const float* __restrict__ bo1,
                     float* __restrict__ bc, float* __restrict__ P, float* __restrict__ q)
{
    int i = blockIdx.x * 256 + threadIdx.x;
    if (i < NB * COUT * CIN) P[i] = 0.f;
    if (i < NB * COUT) q[i] = 0.f;
    if (i < 512) bc[i] = b1[i];
    else if (i < MTOT) bc[i] = bo1[i - 512];
}

// ---------------- merged HMMA GEMM: 128 threads, 64x64 warp tiles ------------
// D(128x128) = Wc(640,512) x Xt^T. 4 warps in 2x2 grid, each 64m x 64n:
// halves duplicated fragment loads vs 4x2/32x64 (smem-port was the bottleneck).
// Single __syncthreads per chunk (serves both visibility + write-safety).
// 3-term: Ahi*Bhi + Ahi*Blo + Alo*Bhi (fp32 accum). bias+relu epilogue,
// rows m0<512 -> y1 (B,512,S); rows m0>=512 -> h1 (B,128,S).
#define STAGE_B  40960          // 4 tiles x 128 rows x 80B
#define TILE_B   10240
#define HSMEM    81920
__global__ __launch_bounds__(128)
void hmma_gemm(const __nv_bfloat16* __restrict__ Wh, const __nv_bfloat16* __restrict__ Wl,
               const __nv_bfloat16* __restrict__ Bh,  const __nv_bfloat16* __restrict__ Bl,
               const float* __restrict__ bias,
               float* __restrict__ Y1, float* __restrict__ H1)
{
    extern __shared__ __align__(128) char smem[];
    const int t = threadIdx.x, wid = t >> 5;
    const int n0 = blockIdx.x * 128, m0 = blockIdx.y * 128, b = blockIdx.z;
    const long brow = (long)b * SS + n0;
    const uint32_t sb = smem_u32(smem);

    const int wm = wid & 1;        // 2 warp rows -> 64 m each
    const int wn = wid >> 1;       // 2 warp cols -> 64 n each

    const __nv_bfloat16* bases[4] = {
        Wh + (long)m0 * 512, Wl + (long)m0 * 512,
        Bh + brow * 512, Bl + brow * 512 };

    auto cpA = [&](int c, int st) {
        const int k0 = c * 32;
#pragma unroll
        for (int i = 0; i < 16; ++i) {
            const int vid = t + i * 128;
            const int tile = vid >> 9;
            const int r    = (vid >> 2) & 127;
            const int v    = vid & 3;
            cp16(sb + st * STAGE_B + tile * TILE_B + r * 80 + v * 16,
                 bases[tile] + (long)r * 512 + k0 + v * 8);
        }
        cp_commit();
    };

    wmma::fragment<wmma::accumulator, 16, 16, 16, float> acc[4][4];
#pragma unroll
    for (int i = 0; i < 4; ++i)
#pragma unroll
        for (int j = 0; j < 4; ++j) wmma::fill_fragment(acc[i][j], 0.0f);

    cpA(0, 0);

    for (int c = 0; c < 16; ++c) {
        const int st = c & 1, nx = st ^ 1;
        cp_wait<0>();              // chunk c (this thread's group) landed
        __syncthreads();           // visibility + stage-nx reads (iter c-1) done
        if (c + 1 < 16) cpA(c + 1, nx);   // flies under MMA(c)

        const __nv_bfloat16* Ah  = (const __nv_bfloat16*)(smem + st * STAGE_B);
        const __nv_bfloat16* Al  = Ah + 5120;
        const __nv_bfloat16* Bhs = Ah + 10240;
        const __nv_bfloat16* Bls = Ah + 15360;

#pragma unroll
        for (int kk = 0; kk < 32; kk += 16) {
            wmma::fragment<wmma::matrix_a, 16, 16, 16, __nv_bfloat16, wmma::row_major> fah[4], fal[4];
#pragma unroll
            for (int i = 0; i < 4; ++i) {
                wmma::load_matrix_sync(fah[i], Ah + (wm * 64 + i * 16) * 40 + kk, 40);
                wmma::load_matrix_sync(fal[i], Al + (wm * 64 + i * 16) * 40 + kk, 40);
            }
#pragma unroll
            for (int j = 0; j < 4; ++j) {
                wmma::fragment<wmma::matrix_b, 16, 16, 16, __nv_bfloat16, wmma::col_major> fbh, fbl;
                wmma::load_matrix_sync(fbh, Bhs + (wn * 64 + j * 16) * 40 + kk, 40);
                wmma::load_matrix_sync(fbl, Bls + (wn * 64 + j * 16) * 40 + kk, 40);
#pragma unroll
                for (int i = 0; i < 4; ++i) {
                    wmma::mma_sync(acc[i][j], fah[i], fbh, acc[i][j]);
                    wmma::mma_sync(acc[i][j], fah[i], fbl, acc[i][j]);
                    wmma::mma_sync(acc[i][j], fal[i], fbh, acc[i][j]);
                }
            }
        }
    }
    __syncthreads();               // last MMA's smem reads done before Dsm reuse

    // ---- epilogue: bias + relu, routed ----
    float* Dsm = (float*)smem;    // [m][n] 128 x 132
#pragma unroll
    for (int i = 0; i < 4; ++i)
#pragma unroll
        for (int j = 0; j < 4; ++j)
            wmma::store_matrix_sync(Dsm + (wm * 64 + i * 16) * 132 + wn * 64 + j * 16,
                                    acc[i][j], 132, wmma::mem_row_major);
    __syncthreads();
    const int r = t;               // 0..127, one output row per thread
    const float bv = bias[m0 + r];
    float* yr = (m0 < 512)
              ? Y1 + ((long)b * CIN + m0 + r) * SS + n0
              : H1 + ((long)b * 128 + (m0 - 512) + r) * SS + n0;
#pragma unroll
    for (int j = 0; j < 128; j += 4) {
        float4 v;
        v.x = fmaxf(Dsm[r * 132 + j + 0] + bv, 0.f);
        v.y = fmaxf(Dsm[r * 132 + j + 1] + bv, 0.f);
        v.z = fmaxf(Dsm[r * 132 + j + 2] + bv, 0.f);
        v.w = fmaxf(Dsm[r * 132 + j + 3] + bv, 0.f);
        *(float4*)(yr + j) = v;
    }
}

// -------- fused occ tail: h2 = relu(Wo2 h1 + b), occ = |Wo3 h2|, q += sums ----
#define W2OFF 0
#define W3OFF 33792
#define H1OFF 51200
#define H2OFF 68096
#define OSMEM 101888
__global__ __launch_bounds__(256)
void occ_tail(const float* __restrict__ h1, const float* __restrict__ wo2,
              const float* __restrict__ bo2, const float* __restrict__ wo3,
              float* __restrict__ occ, float* __restrict__ q)
{
    extern __shared__ __align__(16) char smem[];
    float* W2s = (float*)(smem + W2OFF);   // [64][132]
    float* W3s = (float*)(smem + W3OFF);   // [64][68]
    float* H1s = (float*)(smem + H1OFF);   // [32][132]
    float* H2s = (float*)(smem + H2OFF);   // [64][132]

    const int t = threadIdx.x;
    const int s0 = blockIdx.x * 128, b = blockIdx.z;
    const int tm = t >> 4, tn = t & 15;    // 16 x 16

#pragma unroll
    for (int i = 0; i < 8; ++i) {
        const int vid = t + i * 256;
        const int r = vid >> 5, c4 = (vid & 31) * 4;
        *(float4*)&W2s[r * 132 + c4] = *(const float4*)(wo2 + r * 128 + c4);
    }
#pragma unroll
    for (int i = 0; i < 4; ++i) {
        const int vid = t + i * 256;
        const int r = vid >> 4, c4 = (vid & 15) * 4;
        *(float4*)&W3s[r * 68 + c4] = *(const float4*)(wo3 + r * 64 + c4);
    }

    float acc1[4][8];
#pragma unroll
    for (int i = 0; i < 4; ++i)
#pragma unroll
        for (int j = 0; j < 8; ++j) acc1[i][j] = 0.f;

    for (int c0 = 0; c0 < 128; c0 += 32) {
        __syncthreads();
#pragma unroll
        for (int i = 0; i < 4; ++i) {
            const int vid = t + i * 256;
            const int r = vid >> 5, sc = (vid & 31) * 4;
            *(float4*)&H1s[r * 132 + sc] =
                *(const float4*)(h1 + ((long)b * 128 + c0 + r) * SS + s0 + sc);
        }
        __syncthreads();
#pragma unroll
        for (int kk = 0; kk < 32; ++kk) {
            float a[4], v[8];
#pragma unroll
            for (int i = 0; i < 4; ++i) a[i] = W2s[(tm * 4 + i) * 132 + c0 + kk];
#pragma unroll
            for (int j = 0; j < 8; ++j) v[j] = H1s[kk * 132 + tn * 8 + j];
#pragma unroll
            for (int i = 0; i < 4; ++i)
#pragma unroll
                for (int j = 0; j < 8; ++j) acc1[i][j] += a[i] * v[j];
        }
    }
    __syncthreads();
#pragma unroll
    for (int i = 0; i < 4; ++i) {
        const float bv = bo2[tm * 4 + i];
#pragma unroll
        for (int j = 0; j < 8; ++j)
            H2s[(tm * 4 + i) * 132 + tn * 8 + j] = fmaxf(acc1[i][j] + bv, 0.f);
    }
    __syncthreads();

    float acc2[4][8];
#pragma unroll
    for (int i = 0; i < 4; ++i)
#pragma unroll
        for (int j = 0; j < 8; ++j) acc2[i][j] = 0.f;
#pragma unroll
    for (int kk = 0; kk < 64; ++kk) {
        float a[4], v[8];
#pragma unroll
        for (int i = 0; i < 4; ++i) a[i] = W3s[(tm * 4 + i) * 68 + kk];
#pragma unroll
        for (int j = 0; j < 8; ++j) v[j] = H2s[kk * 132 + tn * 8 + j];
#pragma unroll
        for (int i = 0; i < 4; ++i)
#pragma unroll
            for (int j = 0; j < 8; ++j) acc2[i][j] += a[i] * v[j];
    }
#pragma unroll
    for (int i = 0; i < 4; ++i) {
        const int o = tm * 4 + i;
        float4 v0, v1;
        float* dst = occ + ((long)b * COUT + o) * SS + s0 + tn * 8;
        v0.x = fabsf(acc2[i][0]); v0.y = fabsf(acc2[i][1]);
        v0.z = fabsf(acc2[i][2]); v0.w = fabsf(acc2[i][3]);
        v1.x = fabsf(acc2[i][4]); v1.y = fabsf(acc2[i][5]);
        v1.z = fabsf(acc2[i][6]); v1.w = fabsf(acc2[i][7]);
        *(float4*)dst = v0;
        *(float4*)(dst + 4) = v1;
        float qp = v0.x + v0.y + v0.z + v0.w + v1.x + v1.y + v1.z + v1.w;
#pragma unroll
        for (int off = 8; off > 0; off >>= 1)
            qp += __shfl_xor_sync(0xffffffff, qp, off);
        if (tn == 0) atomicAdd(&q[b * COUT + o], qp * (1.0f / (float)SS));
    }
}

// ------ P[b,o,k] = (1/S) sum_s occ[b,o,s] * y1[b,k,s]  (split-K atomics) ------
__global__ __launch_bounds__(256)
void pool_contract(const float* __restrict__ Occ, const float* __restrict__ Y1,
                   float* __restrict__ P)
{
    const int S = SS;
    const int bz = blockIdx.z;
    const int b  = bz / NSPLIT;
    const int sp = bz % NSPLIT;
    const int chunk = S / NSPLIT;
    const int sbeg  = sp * chunk;

    const float* Ab = Occ + (long)b * COUT * S;
    const float* Fb = Y1  + (long)b * CIN  * S;
    const int n0 = blockIdx.x * 64;

    __shared__ float As[16][64 + 4];
    __shared__ float Bs[16][64 + 4];

    const int t  = threadIdx.x;
    const int tn = t % 16;
    const int tm = t / 16;
    const int lrow = t >> 2;
    const int lk   = (t & 3) * 4;

    float acc[4][4];
#pragma unroll
    for (int i = 0; i < 4; i++)
#pragma unroll
        for (int j = 0; j < 4; j++) acc[i][j] = 0.f;

    for (int s0 = sbeg; s0 < sbeg + chunk; s0 += 16) {
        float4 a4 = *(const float4*)(Ab + (long)lrow * S + s0 + lk);
        As[lk+0][lrow] = a4.x; As[lk+1][lrow] = a4.y;
        As[lk+2][lrow] = a4.z; As[lk+3][lrow] = a4.w;
        float4 f4 = *(const float4*)(Fb + (long)(n0 + lrow) * S + s0 + lk);
        Bs[lk+0][lrow] = f4.x; Bs[lk+1][lrow] = f4.y;
        Bs[lk+2][lrow] = f4.z; Bs[lk+3][lrow] = f4.w;
        __syncthreads();

#pragma unroll
        for (int kk = 0; kk < 16; kk++) {
            float4 av = *(const float4*)&As[kk][tm * 4];
            float4 bv = *(const float4*)&Bs[kk][tn * 4];
            float a[4] = {av.x, av.y, av.z, av.w};
            float c[4] = {bv.x, bv.y, bv.z, bv.w};
#pragma unroll
            for (int i = 0; i < 4; i++)
#pragma unroll
                for (int j = 0; j < 4; j++) acc[i][j] += a[i] * c[j];
        }
        __syncthreads();
    }

    const float scale = 1.0f / (float)S;
#pragma unroll
    for (int i = 0; i < 4; i++)
#pragma unroll
        for (int j = 0; j < 4; j++) {
            const int o = tm * 4 + i;
            const int k = n0 + tn * 4 + j;
            atomicAdd(&P[((long)b * COUT + o) * CIN + k], acc[i][j] * scale);
        }
}

// ------ out[b,o,c] = sum_k P[b,o,k]*W2[c,k] + q[b,o]*b2[c] -------------------
__global__ __launch_bounds__(256)
void fin_gemm(const float* __restrict__ P, const float* __restrict__ q,
              const float* __restrict__ W2, const float* __restrict__ b2,
              float* __restrict__ out)
{
    const int b = blockIdx.z, c0 = blockIdx.x * 64;
    __shared__ float Pt[64][68];
    __shared__ float Wt[64][68];
    const int t = threadIdx.x;
    const int tm = t >> 4, tn = t & 15;

    float acc[4][4];
#pragma unroll
    for (int i = 0; i < 4; i++)
#pragma unroll
        for (int j = 0; j < 4; j++) acc[i][j] = 0.f;

    for (int k0 = 0; k0 < CIN; k0 += 64) {
#pragma unroll
        for (int i = 0; i < 4; ++i) {
            const int r  = (t >> 4) + i * 16;
            const int kc = (t & 15) * 4;
            *(float4*)&Pt[r][kc] = *(const float4*)(P + ((long)b * COUT + r) * CIN + k0 + kc);
            *(float4*)&Wt[r][kc] = *(const float4*)(W2 + (long)(c0 + r) * CIN + k0 + kc);
        }
        __syncthreads();
#pragma unroll
        for (int kk = 0; kk < 64; ++kk) {
            float a[4], w[4];
#pragma unroll
            for (int i = 0; i < 4; ++i) a[i] = Pt[tm * 4 + i][kk];
#pragma unroll
            for (int j = 0; j < 4; ++j) w[j] = Wt[tn * 4 + j][kk];
#pragma unroll
            for (int i = 0; i < 4; ++i)
#pragma unroll
                for (int j = 0; j < 4; ++j) acc[i][j] += a[i] * w[j];
        }
        __syncthreads();
    }

#pragma unroll
    for (int i = 0; i < 4; ++i) {
        const int o = tm * 4 + i;
        const float qv = q[b * COUT + o];
#pragma unroll
        for (int j = 0; j < 4; ++j) {
            const int c = c0 + tn * 4 + j;
            out[((long)b * COUT + o) * CIN + c] = acc[i][j] + qv * b2[c];
        }
    }
}

// -----------------------------------------------------------------------------
extern "C" void kernel_launch(void* const* d_in, const int* in_sizes, int n_in,
                              void* d_out, int out_size)
{
    const float* x      = (const float*)d_in[0];
    const float* w_add1 = (const float*)d_in[1];
    const float* b_add1 = (const float*)d_in[2];
    const float* w_add2 = (const float*)d_in[3];
    const float* b_add2 = (const float*)d_in[4];
    const float* w_occ1 = (const float*)d_in[5];
    const float* b_occ1 = (const float*)d_in[6];
    const float* w_occ2 = (const float*)d_in[7];
    const float* b_occ2 = (const float*)d_in[8];
    const float* w_occ3 = (const float*)d_in[9];
    float* out = (float*)d_out;

    __nv_bfloat16 *xth, *xtl, *wch, *wcl;
    float *y1, *h1, *occ, *P, *q, *bc;
    cudaGetSymbolAddress((void**)&xth, g_xt_hi);
    cudaGetSymbolAddress((void**)&xtl, g_xt_lo);
    cudaGetSymbolAddress((void**)&y1,  g_y1);
    cudaGetSymbolAddress((void**)&h1,  g_h1);
    cudaGetSymbolAddress((void**)&occ, g_occ);
    cudaGetSymbolAddress((void**)&P,   g_P);
    cudaGetSymbolAddress((void**)&q,   g_q);
    cudaGetSymbolAddress((void**)&wch, g_wch);
    cudaGetSymbolAddress((void**)&wcl, g_wcl);
    cudaGetSymbolAddress((void**)&bc,  g_bc);

    cudaFuncSetAttribute(hmma_gemm, cudaFuncAttributeMaxDynamicSharedMemorySize, HSMEM);
    cudaFuncSetAttribute(occ_tail,  cudaFuncAttributeMaxDynamicSharedMemorySize, OSMEM);

    // launches #1-#3 (pre), #4 = hmma_gemm (ncu captures launch #4)
    transpose_split<<<dim3(SS/32, CIN/32, NB), dim3(32, 8)>>>(x, xth, xtl);
    wsplit_all<<<(MTOT*CIN + 255) / 256, 256>>>(w_add1, w_occ1, wch, wcl);
    prep<<<(NB*COUT*CIN + 255) / 256, 256>>>(b_add1, b_occ1, bc, P, q);

    // merged add1 + occ1: rows 0..511 -> y1, rows 512..639 -> h1
    hmma_gemm<<<dim3(SS/128, MTOT/128, NB), 128, HSMEM>>>(wch, wcl, xth, xtl, bc, y1, h1);

    // fused occ tail (occ2 + occ3 + q)
    occ_tail<<<dim3(SS/128, 1, NB), 256, OSMEM>>>(h1, w_occ2, b_occ2, w_occ3, occ, q);

    // P = (1/S) occ . y1^T
    pool_contract<<<dim3(CIN/64, 1, NB * NSPLIT), 256>>>(occ, y1, P);

    // out = P . W2^T + q b2^T
    fin_gemm<<<dim3(CIN/64, 1, NB), 256>>>(P, q, w_add2, b_add2, out);
}

// round 12
// speedup vs baseline: 1.3615x; 1.1766x over previous
#include <cuda_runtime.h>
#include <cuda_bf16.h>
#include <cuda_fp16.h>
#include <mma.h>
#include <cstdint>

using namespace nvcuda;

#define NB   4
#define CIN  512
#define COUT 64
#define SS   16384   // T*H*W
#define NSPLIT 32
#define MTOT 640     // 512 (add1) + 128 (occ1) fused rows

// ---------------- scratch (device globals; no allocs allowed) ----------------
__device__ __half g_xt_hi[(size_t)NB * SS * CIN];   // x^T fp16 hi
__device__ __half g_xt_lo[(size_t)NB * SS * CIN];   // x^T fp16 lo (residual)
__device__ float g_y1  [(size_t)NB * CIN * SS];     // relu(add1) fp32 (B,512,S)
__device__ float g_h1  [(size_t)NB * 128 * SS];     // relu(occ1)
__device__ float g_occ [(size_t)NB *  64 * SS];
__device__ float g_P   [(size_t)NB * COUT * CIN];
__device__ float g_q   [(size_t)NB * COUT];
__device__ __half g_wch[MTOT * CIN];                // concat W rows, fp16
__device__ float g_bc[MTOT];                        // concat bias

// ---------------- helpers ----------------------------------------------------
__device__ __forceinline__ uint32_t smem_u32(const void* p) {
    uint32_t a;
    asm("{ .reg .u64 t; cvta.to.shared.u64 t, %1; cvt.u32.u64 %0, t; }" : "=r"(a) : "l"(p));
    return a;
}
__device__ __forceinline__ void cp16(uint32_t dst, const void* src) {
    asm volatile("cp.async.cg.shared.global [%0], [%1], 16;" :: "r"(dst), "l"(src));
}
__device__ __forceinline__ void cp_commit() {
    asm volatile("cp.async.commit_group;" ::: "memory");
}
template<int N>
__device__ __forceinline__ void cp_wait() {
    asm volatile("cp.async.wait_group %0;" :: "n"(N) : "memory");
}

// ---------------- pre-passes (3 launches so hmma_gemm is launch #4) ----------
__global__ __launch_bounds__(256)
void transpose_split(const float* __restrict__ X,
                     __half* __restrict__ H, __half* __restrict__ L)
{
    __shared__ float tile[32][33];
    const int s0 = blockIdx.x * 32, c0 = blockIdx.y * 32, b = blockIdx.z;
    const int tx = threadIdx.x, ty = threadIdx.y;   // 32 x 8
    const float* Xb = X + ((long)b * CIN + c0) * SS + s0;
#pragma unroll
    for (int j = 0; j < 4; ++j)
        tile[ty + 8 * j][tx] = Xb[(long)(ty + 8 * j) * SS + tx];
    __syncthreads();
#pragma unroll
    for (int j = 0; j < 4; ++j) {
        const int s = ty + 8 * j;
        float v = tile[tx][s];
        const long off = ((long)b * SS + s0 + s) * CIN + c0 + tx;
        __half hi = __float2half(v);
        H[off] = hi;
        L[off] = __float2half(v - __half2float(hi));
    }
}

__global__ void wsplit_all(const float* __restrict__ W1, const float* __restrict__ Wo1,
                           __half* __restrict__ H)
{
    int i = blockIdx.x * 256 + threadIdx.x;
    if (i >= MTOT * CIN) return;
    float v = (i < 512 * CIN) ? W1[i] : Wo1[i - 512 * CIN];
    H[i] = __float2half(v);
}

__global__ void prep(const float* __restrict__ b1, const float* __restrict__ bo1,
                     float* __restrict__ bc, float* __restrict__ P, float* __restrict__ q)
{
    int i = blockIdx.x * 256 + threadIdx.x;
    if (i < NB * COUT * CIN) P[i] = 0.f;
    if (i < NB * COUT) q[i] = 0.f;
    if (i < 512) bc[i] = b1[i];
    else if (i < MTOT) bc[i] = bo1[i - 512];
}

// ---------------- merged HMMA GEMM: fp16 2-term, 128 thr, 64x64 warp tiles ---
// D(128x128) = Wc(640,512) x Xt^T.  2-term: Wh*Xh + Wh*Xl (fp32 accum).
// Smem-port was the bottleneck (R11 model validated): dropping the W-lo
// operand cuts frag reads 32->24 and cp tiles 4->3 per chunk.
// rows m0<512 -> y1 (B,512,S); rows m0>=512 -> h1 (B,128,S). bias+relu.
#define STAGE_B  30720          // 3 tiles x 128 rows x 80B
#define TILE_B   10240
#define HSMEM    67584          // max(mainloop 61440, epilogue Dsm 128x132x4)
__global__ __launch_bounds__(128)
void hmma_gemm(const __half* __restrict__ Wh,
               const __half* __restrict__ Bh, const __half* __restrict__ Bl,
               const float* __restrict__ bias,
               float* __restrict__ Y1, float* __restrict__ H1)
{
    extern __shared__ __align__(128) char smem[];
    const int t = threadIdx.x, wid = t >> 5;
    const int n0 = blockIdx.x * 128, m0 = blockIdx.y * 128, b = blockIdx.z;
    const long brow = (long)b * SS + n0;
    const uint32_t sb = smem_u32(smem);

    const int wm = wid & 1;        // 2 warp rows -> 64 m each
    const int wn = wid >> 1;       // 2 warp cols -> 64 n each

    const __half* bases[3] = {
        Wh + (long)m0 * 512, Bh + brow * 512, Bl + brow * 512 };

    auto cpA = [&](int c, int st) {
        const int k0 = c * 32;
#pragma unroll
        for (int i = 0; i < 12; ++i) {
            const int vid = t + i * 128;
            const int tile = vid >> 9;           // 0=Wh 1=Xh 2=Xl
            const int r    = (vid >> 2) & 127;
            const int v    = vid & 3;
            cp16(sb + st * STAGE_B + tile * TILE_B + r * 80 + v * 16,
                 bases[tile] + (long)r * 512 + k0 + v * 8);
        }
        cp_commit();
    };

    wmma::fragment<wmma::accumulator, 16, 16, 16, float> acc[4][4];
#pragma unroll
    for (int i = 0; i < 4; ++i)
#pragma unroll
        for (int j = 0; j < 4; ++j) wmma::fill_fragment(acc[i][j], 0.0f);

    cpA(0, 0);

    for (int c = 0; c < 16; ++c) {
        const int st = c & 1, nx = st ^ 1;
        cp_wait<0>();              // chunk c (this thread's group) landed
        __syncthreads();           // visibility + stage-nx reads (iter c-1) done
        if (c + 1 < 16) cpA(c + 1, nx);   // flies under MMA(c)

        const __half* Ah  = (const __half*)(smem + st * STAGE_B);
        const __half* Bhs = Ah + 5120;
        const __half* Bls = Ah + 10240;

#pragma unroll
        for (int kk = 0; kk < 32; kk += 16) {
            wmma::fragment<wmma::matrix_a, 16, 16, 16, __half, wmma::row_major> fah[4];
#pragma unroll
            for (int i = 0; i < 4; ++i)
                wmma::load_matrix_sync(fah[i], Ah + (wm * 64 + i * 16) * 40 + kk, 40);
#pragma unroll
            for (int j = 0; j < 4; ++j) {
                wmma::fragment<wmma::matrix_b, 16, 16, 16, __half, wmma::col_major> fbh, fbl;
                wmma::load_matrix_sync(fbh, Bhs + (wn * 64 + j * 16) * 40 + kk, 40);
                wmma::load_matrix_sync(fbl, Bls + (wn * 64 + j * 16) * 40 + kk, 40);
#pragma unroll
                for (int i = 0; i < 4; ++i) {
                    wmma::mma_sync(acc[i][j], fah[i], fbh, acc[i][j]);
                    wmma::mma_sync(acc[i][j], fah[i], fbl, acc[i][j]);
                }
            }
        }
    }
    __syncthreads();               // last MMA's smem reads done before Dsm reuse

    // ---- epilogue: bias + relu, routed ----
    float* Dsm = (float*)smem;    // [m][n] 128 x 132
#pragma unroll
    for (int i = 0; i < 4; ++i)
#pragma unroll
        for (int j = 0; j < 4; ++j)
            wmma::store_matrix_sync(Dsm + (wm * 64 + i * 16) * 132 + wn * 64 + j * 16,
                                    acc[i][j], 132, wmma::mem_row_major);
    __syncthreads();
    const int r = t;               // 0..127, one output row per thread
    const float bv = bias[m0 + r];
    float* yr = (m0 < 512)
              ? Y1 + ((long)b * CIN + m0 + r) * SS + n0
              : H1 + ((long)b * 128 + (m0 - 512) + r) * SS + n0;
#pragma unroll
    for (int j = 0; j < 128; j += 4) {
        float4 v;
        v.x = fmaxf(Dsm[r * 132 + j + 0] + bv, 0.f);
        v.y = fmaxf(Dsm[r * 132 + j + 1] + bv, 0.f);
        v.z = fmaxf(Dsm[r * 132 + j + 2] + bv, 0.f);
        v.w = fmaxf(Dsm[r * 132 + j + 3] + bv, 0.f);
        *(float4*)(yr + j) = v;
    }
}

// -------- fused occ tail: h2 = relu(Wo2 h1 + b), occ = |Wo3 h2|, q += sums ----
#define W2OFF 0
#define W3OFF 33792
#define H1OFF 51200
#define H2OFF 68096
#define OSMEM 101888
__global__ __launch_bounds__(256)
void occ_tail(const float* __restrict__ h1, const float* __restrict__ wo2,
              const float* __restrict__ bo2, const float* __restrict__ wo3,
              float* __restrict__ occ, float* __restrict__ q)
{
    extern __shared__ __align__(16) char smem[];
    float* W2s = (float*)(smem + W2OFF);   // [64][132]
    float* W3s = (float*)(smem + W3OFF);   // [64][68]
    float* H1s = (float*)(smem + H1OFF);   // [32][132]
    float* H2s = (float*)(smem + H2OFF);   // [64][132]

    const int t = threadIdx.x;
    const int s0 = blockIdx.x * 128, b = blockIdx.z;
    const int tm = t >> 4, tn = t & 15;    // 16 x 16

#pragma unroll
    for (int i = 0; i < 8; ++i) {
        const int vid = t + i * 256;
        const int r = vid >> 5, c4 = (vid & 31) * 4;
        *(float4*)&W2s[r * 132 + c4] = *(const float4*)(wo2 + r * 128 + c4);
    }
#pragma unroll
    for (int i = 0; i < 4; ++i) {
        const int vid = t + i * 256;
        const int r = vid >> 4, c4 = (vid & 15) * 4;
        *(float4*)&W3s[r * 68 + c4] = *(const float4*)(wo3 + r * 64 + c4);
    }

    float acc1[4][8];
#pragma unroll
    for (int i = 0; i < 4; ++i)
#pragma unroll
        for (int j = 0; j < 8; ++j) acc1[i][j] = 0.f;

    for (int c0 = 0; c0 < 128; c0 += 32) {
        __syncthreads();
#pragma unroll
        for (int i = 0; i < 4; ++i) {
            const int vid = t + i * 256;
            const int r = vid >> 5, sc = (vid & 31) * 4;
            *(float4*)&H1s[r * 132 + sc] =
                *(const float4*)(h1 + ((long)b * 128 + c0 + r) * SS + s0 + sc);
        }
        __syncthreads();
#pragma unroll
        for (int kk = 0; kk < 32; ++kk) {
            float a[4], v[8];
#pragma unroll
            for (int i = 0; i < 4; ++i) a[i] = W2s[(tm * 4 + i) * 132 + c0 + kk];
#pragma unroll
            for (int j = 0; j < 8; ++j) v[j] = H1s[kk * 132 + tn * 8 + j];
#pragma unroll
            for (int i = 0; i < 4; ++i)
#pragma unroll
                for (int j = 0; j < 8; ++j) acc1[i][j] += a[i] * v[j];
        }
    }
    __syncthreads();
#pragma unroll
    for (int i = 0; i < 4; ++i) {
        const float bv = bo2[tm * 4 + i];
#pragma unroll
        for (int j = 0; j < 8; ++j)
            H2s[(tm * 4 + i) * 132 + tn * 8 + j] = fmaxf(acc1[i][j] + bv, 0.f);
    }
    __syncthreads();

    float acc2[4][8];
#pragma unroll
    for (int i = 0; i < 4; ++i)
#pragma unroll
        for (int j = 0; j < 8; ++j) acc2[i][j] = 0.f;
#pragma unroll
    for (int kk = 0; kk < 64; ++kk) {
        float a[4], v[8];
#pragma unroll
        for (int i = 0; i < 4; ++i) a[i] = W3s[(tm * 4 + i) * 68 + kk];
#pragma unroll
        for (int j = 0; j < 8; ++j) v[j] = H2s[kk * 132 + tn * 8 + j];
#pragma unroll
        for (int i = 0; i < 4; ++i)
#pragma unroll
            for (int j = 0; j < 8; ++j) acc2[i][j] += a[i] * v[j];
    }
#pragma unroll
    for (int i = 0; i < 4; ++i) {
        const int o = tm * 4 + i;
        float4 v0, v1;
        float* dst = occ + ((long)b * COUT + o) * SS + s0 + tn * 8;
        v0.x = fabsf(acc2[i][0]); v0.y = fabsf(acc2[i][1]);
        v0.z = fabsf(acc2[i][2]); v0.w = fabsf(acc2[i][3]);
        v1.x = fabsf(acc2[i][4]); v1.y = fabsf(acc2[i][5]);
        v1.z = fabsf(acc2[i][6]); v1.w = fabsf(acc2[i][7]);
        *(float4*)dst = v0;
        *(float4*)(dst + 4) = v1;
        float qp = v0.x + v0.y + v0.z + v0.w + v1.x + v1.y + v1.z + v1.w;
#pragma unroll
        for (int off = 8; off > 0; off >>= 1)
            qp += __shfl_xor_sync(0xffffffff, qp, off);
        if (tn == 0) atomicAdd(&q[b * COUT + o], qp * (1.0f / (float)SS));
    }
}

// ------ P[b,o,k] = (1/S) sum_s occ[b,o,s] * y1[b,k,s]  (split-K atomics) ------
__global__ __launch_bounds__(256)
void pool_contract(const float* __restrict__ Occ, const float* __restrict__ Y1,
                   float* __restrict__ P)
{
    const int S = SS;
    const int bz = blockIdx.z;
    const int b  = bz / NSPLIT;
    const int sp = bz % NSPLIT;
    const int chunk = S / NSPLIT;
    const int sbeg  = sp * chunk;

    const float* Ab = Occ + (long)b * COUT * S;
    const float* Fb = Y1  + (long)b * CIN  * S;
    const int n0 = blockIdx.x * 64;

    __shared__ float As[16][64 + 4];
    __shared__ float Bs[16][64 + 4];

    const int t  = threadIdx.x;
    const int tn = t % 16;
    const int tm = t / 16;
    const int lrow = t >> 2;
    const int lk   = (t & 3) * 4;

    float acc[4][4];
#pragma unroll
    for (int i = 0; i < 4; i++)
#pragma unroll
        for (int j = 0; j < 4; j++) acc[i][j] = 0.f;

    for (int s0 = sbeg; s0 < sbeg + chunk; s0 += 16) {
        float4 a4 = *(const float4*)(Ab + (long)lrow * S + s0 + lk);
        As[lk+0][lrow] = a4.x; As[lk+1][lrow] = a4.y;
        As[lk+2][lrow] = a4.z; As[lk+3][lrow] = a4.w;
        float4 f4 = *(const float4*)(Fb + (long)(n0 + lrow) * S + s0 + lk);
        Bs[lk+0][lrow] = f4.x; Bs[lk+1][lrow] = f4.y;
        Bs[lk+2][lrow] = f4.z; Bs[lk+3][lrow] = f4.w;
        __syncthreads();

#pragma unroll
        for (int kk = 0; kk < 16; kk++) {
            float4 av = *(const float4*)&As[kk][tm * 4];
            float4 bv = *(const float4*)&Bs[kk][tn * 4];
            float a[4] = {av.x, av.y, av.z, av.w};
            float c[4] = {bv.x, bv.y, bv.z, bv.w};
#pragma unroll
            for (int i = 0; i < 4; i++)
#pragma unroll
                for (int j = 0; j < 4; j++) acc[i][j] += a[i] * c[j];
        }
        __syncthreads();
    }

    const float scale = 1.0f / (float)S;
#pragma unroll
    for (int i = 0; i < 4; i++)
#pragma unroll
        for (int j = 0; j < 4; j++) {
            const int o = tm * 4 + i;
            const int k = n0 + tn * 4 + j;
            atomicAdd(&P[((long)b * COUT + o) * CIN + k], acc[i][j] * scale);
        }
}

// ------ out[b,o,c] = sum_k P[b,o,k]*W2[c,k] + q[b,o]*b2[c] -------------------
__global__ __launch_bounds__(256)
void fin_gemm(const float* __restrict__ P, const float* __restrict__ q,
              const float* __restrict__ W2, const float* __restrict__ b2,
              float* __restrict__ out)
{
    const int b = blockIdx.z, c0 = blockIdx.x * 64;
    __shared__ float Pt[64][68];
    __shared__ float Wt[64][68];
    const int t = threadIdx.x;
    const int tm = t >> 4, tn = t & 15;

    float acc[4][4];
#pragma unroll
    for (int i = 0; i < 4; i++)
#pragma unroll
        for (int j = 0; j < 4; j++) acc[i][j] = 0.f;

    for (int k0 = 0; k0 < CIN; k0 += 64) {
#pragma unroll
        for (int i = 0; i < 4; ++i) {
            const int r  = (t >> 4) + i * 16;
            const int kc = (t & 15) * 4;
            *(float4*)&Pt[r][kc] = *(const float4*)(P + ((long)b * COUT + r) * CIN + k0 + kc);
            *(float4*)&Wt[r][kc] = *(const float4*)(W2 + (long)(c0 + r) * CIN + k0 + kc);
        }
        __syncthreads();
#pragma unroll
        for (int kk = 0; kk < 64; ++kk) {
            float a[4], w[4];
#pragma unroll
            for (int i = 0; i < 4; ++i) a[i] = Pt[tm * 4 + i][kk];
#pragma unroll
            for (int j = 0; j < 4; ++j) w[j] = Wt[tn * 4 + j][kk];
#pragma unroll
            for (int i = 0; i < 4; ++i)
#pragma unroll
                for (int j = 0; j < 4; ++j) acc[i][j] += a[i] * w[j];
        }
        __syncthreads();
    }

#pragma unroll
    for (int i = 0; i < 4; ++i) {
        const int o = tm * 4 + i;
        const float qv = q[b * COUT + o];
#pragma unroll
        for (int j = 0; j < 4; ++j) {
            const int c = c0 + tn * 4 + j;
            out[((long)b * COUT + o) * CIN + c] = acc[i][j] + qv * b2[c];
        }
    }
}

// -----------------------------------------------------------------------------
extern "C" void kernel_launch(void* const* d_in, const int* in_sizes, int n_in,
                              void* d_out, int out_size)
{
    const float* x      = (const float*)d_in[0];
    const float* w_add1 = (const float*)d_in[1];
    const float* b_add1 = (const float*)d_in[2];
    const float* w_add2 = (const float*)d_in[3];
    const float* b_add2 = (const float*)d_in[4];
    const float* w_occ1 = (const float*)d_in[5];
    const float* b_occ1 = (const float*)d_in[6];
    const float* w_occ2 = (const float*)d_in[7];
    const float* b_occ2 = (const float*)d_in[8];
    const float* w_occ3 = (const float*)d_in[9];
    float* out = (float*)d_out;

    __half *xth, *xtl, *wch;
    float *y1, *h1, *occ, *P, *q, *bc;
    cudaGetSymbolAddress((void**)&xth, g_xt_hi);
    cudaGetSymbolAddress((void**)&xtl, g_xt_lo);
    cudaGetSymbolAddress((void**)&y1,  g_y1);
    cudaGetSymbolAddress((void**)&h1,  g_h1);
    cudaGetSymbolAddress((void**)&occ, g_occ);
    cudaGetSymbolAddress((void**)&P,   g_P);
    cudaGetSymbolAddress((void**)&q,   g_q);
    cudaGetSymbolAddress((void**)&wch, g_wch);
    cudaGetSymbolAddress((void**)&bc,  g_bc);

    cudaFuncSetAttribute(hmma_gemm, cudaFuncAttributeMaxDynamicSharedMemorySize, HSMEM);
    cudaFuncSetAttribute(occ_tail,  cudaFuncAttributeMaxDynamicSharedMemorySize, OSMEM);

    // launches #1-#3 (pre), #4 = hmma_gemm (ncu captures launch #4)
    transpose_split<<<dim3(SS/32, CIN/32, NB), dim3(32, 8)>>>(x, xth, xtl);
    wsplit_all<<<(MTOT*CIN + 255) / 256, 256>>>(w_add1, w_occ1, wch);
    prep<<<(NB*COUT*CIN + 255) / 256, 256>>>(b_add1, b_occ1, bc, P, q);

    // merged add1 + occ1: rows 0..511 -> y1, rows 512..639 -> h1
    hmma_gemm<<<dim3(SS/128, MTOT/128, NB), 128, HSMEM>>>(wch, xth, xtl, bc, y1, h1);

    // fused occ tail (occ2 + occ3 + q)
    occ_tail<<<dim3(SS/128, 1, NB), 256, OSMEM>>>(h1, w_occ2, b_occ2, w_occ3, occ, q);

    // P = (1/S) occ . y1^T
    pool_contract<<<dim3(CIN/64, 1, NB * NSPLIT), 256>>>(occ, y1, P);

    // out = P . W2^T + q b2^T
    fin_gemm<<<dim3(CIN/64, 1, NB), 256>>>(P, q, w_add2, b_add2, out);
}

// round 13
// speedup vs baseline: 1.4312x; 1.0512x over previous
#include <cuda_runtime.h>
#include <cuda_fp16.h>
#include <mma.h>
#include <cstdint>

using namespace nvcuda;

#define NB   4
#define CIN  512
#define COUT 64
#define SS   16384   // T*H*W
#define NSPLIT 32
#define MTOT 640     // 512 (add1) + 128 (occ1) fused rows

// ---------------- scratch (device globals; no allocs allowed) ----------------
__device__ __half g_xt_hi[(size_t)NB * SS * CIN];   // x^T fp16 hi
__device__ __half g_xt_lo[(size_t)NB * SS * CIN];   // x^T fp16 lo (residual)
__device__ __half g_y1 [(size_t)NB * CIN * SS];     // relu(add1) fp16 (B,512,S)
__device__ __half g_h1 [(size_t)NB * 128 * SS];     // relu(occ1)  fp16
__device__ __half g_occ[(size_t)NB *  64 * SS];     // |occ3|      fp16
__device__ float g_P   [(size_t)NB * COUT * CIN];
__device__ float g_q   [(size_t)NB * COUT];
__device__ __half g_wch[MTOT * CIN];                // concat W rows, fp16
__device__ float g_bc[MTOT];                        // concat bias

// ---------------- helpers ----------------------------------------------------
__device__ __forceinline__ uint32_t smem_u32(const void* p) {
    uint32_t a;
    asm("{ .reg .u64 t; cvta.to.shared.u64 t, %1; cvt.u32.u64 %0, t; }" : "=r"(a) : "l"(p));
    return a;
}
__device__ __forceinline__ void cp16(uint32_t dst, const void* src) {
    asm volatile("cp.async.cg.shared.global [%0], [%1], 16;" :: "r"(dst), "l"(src));
}
__device__ __forceinline__ void cp_commit() {
    asm volatile("cp.async.commit_group;" ::: "memory");
}
template<int N>
__device__ __forceinline__ void cp_wait() {
    asm volatile("cp.async.wait_group %0;" :: "n"(N) : "memory");
}
union H4 { uint2 u; __half h[4]; };
union H8 { uint4 u; __half h[8]; };

// ---------------- pre-passes (3 launches so hmma_gemm is launch #4) ----------
__global__ __launch_bounds__(256)
void transpose_split(const float* __restrict__ X,
                     __half* __restrict__ H, __half* __restrict__ L)
{
    __shared__ float tile[32][33];
    const int s0 = blockIdx.x * 32, c0 = blockIdx.y * 32, b = blockIdx.z;
    const int tx = threadIdx.x, ty = threadIdx.y;   // 32 x 8
    const float* Xb = X + ((long)b * CIN + c0) * SS + s0;
#pragma unroll
    for (int j = 0; j < 4; ++j)
        tile[ty + 8 * j][tx] = Xb[(long)(ty + 8 * j) * SS + tx];
    __syncthreads();
#pragma unroll
    for (int j = 0; j < 4; ++j) {
        const int s = ty + 8 * j;
        float v = tile[tx][s];
        const long off = ((long)b * SS + s0 + s) * CIN + c0 + tx;
        __half hi = __float2half(v);
        H[off] = hi;
        L[off] = __float2half(v - __half2float(hi));
    }
}

__global__ void wsplit_all(const float* __restrict__ W1, const float* __restrict__ Wo1,
                           __half* __restrict__ H)
{
    int i = blockIdx.x * 256 + threadIdx.x;
    if (i >= MTOT * CIN) return;
    float v = (i < 512 * CIN) ? W1[i] : Wo1[i - 512 * CIN];
    H[i] = __float2half(v);
}

__global__ void prep(const float* __restrict__ b1, const float* __restrict__ bo1,
                     float* __restrict__ bc, float* __restrict__ P, float* __restrict__ q)
{
    int i = blockIdx.x * 256 + threadIdx.x;
    if (i < NB * COUT * CIN) P[i] = 0.f;
    if (i < NB * COUT) q[i] = 0.f;
    if (i < 512) bc[i] = b1[i];
    else if (i < MTOT) bc[i] = bo1[i - 512];
}

// ---------------- merged HMMA GEMM: fp16 2-term, 128 thr, 64x64 warp tiles ---
// D(128x128) = Wc(640,512) x Xt^T.  2-term: Wh*Xh + Wh*Xl (fp32 accum).
// rows m0<512 -> y1 fp16 (B,512,S); rows m0>=512 -> h1 fp16 (B,128,S). bias+relu.
#define STAGE_B  30720          // 3 tiles x 128 rows x 80B
#define TILE_B   10240
#define HSMEM    67584          // max(mainloop 61440, epilogue Dsm 128x132x4)
__global__ __launch_bounds__(128)
void hmma_gemm(const __half* __restrict__ Wh,
               const __half* __restrict__ Bh, const __half* __restrict__ Bl,
               const float* __restrict__ bias,
               __half* __restrict__ Y1, __half* __restrict__ H1)
{
    extern __shared__ __align__(128) char smem[];
    const int t = threadIdx.x, wid = t >> 5;
    const int n0 = blockIdx.x * 128, m0 = blockIdx.y * 128, b = blockIdx.z;
    const long brow = (long)b * SS + n0;
    const uint32_t sb = smem_u32(smem);

    const int wm = wid & 1;        // 2 warp rows -> 64 m each
    const int wn = wid >> 1;       // 2 warp cols -> 64 n each

    const __half* bases[3] = {
        Wh + (long)m0 * 512, Bh + brow * 512, Bl + brow * 512 };

    auto cpA = [&](int c, int st) {
        const int k0 = c * 32;
#pragma unroll
        for (int i = 0; i < 12; ++i) {
            const int vid = t + i * 128;
            const int tile = vid >> 9;           // 0=Wh 1=Xh 2=Xl
            const int r    = (vid >> 2) & 127;
            const int v    = vid & 3;
            cp16(sb + st * STAGE_B + tile * TILE_B + r * 80 + v * 16,
                 bases[tile] + (long)r * 512 + k0 + v * 8);
        }
        cp_commit();
    };

    wmma::fragment<wmma::accumulator, 16, 16, 16, float> acc[4][4];
#pragma unroll
    for (int i = 0; i < 4; ++i)
#pragma unroll
        for (int j = 0; j < 4; ++j) wmma::fill_fragment(acc[i][j], 0.0f);

    cpA(0, 0);

    for (int c = 0; c < 16; ++c) {
        const int st = c & 1, nx = st ^ 1;
        cp_wait<0>();              // chunk c (this thread's group) landed
        __syncthreads();           // visibility + stage-nx reads (iter c-1) done
        if (c + 1 < 16) cpA(c + 1, nx);   // flies under MMA(c)

        const __half* Ah  = (const __half*)(smem + st * STAGE_B);
        const __half* Bhs = Ah + 5120;
        const __half* Bls = Ah + 10240;

#pragma unroll
        for (int kk = 0; kk < 32; kk += 16) {
            wmma::fragment<wmma::matrix_a, 16, 16, 16, __half, wmma::row_major> fah[4];
#pragma unroll
            for (int i = 0; i < 4; ++i)
                wmma::load_matrix_sync(fah[i], Ah + (wm * 64 + i * 16) * 40 + kk, 40);
#pragma unroll
            for (int j = 0; j < 4; ++j) {
                wmma::fragment<wmma::matrix_b, 16, 16, 16, __half, wmma::col_major> fbh, fbl;
                wmma::load_matrix_sync(fbh, Bhs + (wn * 64 + j * 16) * 40 + kk, 40);
                wmma::load_matrix_sync(fbl, Bls + (wn * 64 + j * 16) * 40 + kk, 40);
#pragma unroll
                for (int i = 0; i < 4; ++i) {
                    wmma::mma_sync(acc[i][j], fah[i], fbh, acc[i][j]);
                    wmma::mma_sync(acc[i][j], fah[i], fbl, acc[i][j]);
                }
            }
        }
    }
    __syncthreads();               // last MMA's smem reads done before Dsm reuse

    // ---- epilogue: bias + relu, fp16 output, routed ----
    float* Dsm = (float*)smem;    // [m][n] 128 x 132
#pragma unroll
    for (int i = 0; i < 4; ++i)
#pragma unroll
        for (int j = 0; j < 4; ++j)
            wmma::store_matrix_sync(Dsm + (wm * 64 + i * 16) * 132 + wn * 64 + j * 16,
                                    acc[i][j], 132, wmma::mem_row_major);
    __syncthreads();
    const int r = t;               // 0..127, one output row per thread
    const float bv = bias[m0 + r];
    __half* yr = (m0 < 512)
               ? Y1 + ((long)b * CIN + m0 + r) * SS + n0
               : H1 + ((long)b * 128 + (m0 - 512) + r) * SS + n0;
#pragma unroll
    for (int j = 0; j < 128; j += 8) {
        H8 o;
#pragma unroll
        for (int e = 0; e < 8; ++e)
            o.h[e] = __float2half(fmaxf(Dsm[r * 132 + j + e] + bv, 0.f));
        *(uint4*)(yr + j) = o.u;
    }
}

// -------- fused occ tail: h2 = relu(Wo2 h1 + b), occ = |Wo3 h2|, q += sums ----
#define W2OFF 0
#define W3OFF 33792
#define H1OFF 51200
#define H2OFF 68096
#define OSMEM 101888
__global__ __launch_bounds__(256)
void occ_tail(const __half* __restrict__ h1, const float* __restrict__ wo2,
              const float* __restrict__ bo2, const float* __restrict__ wo3,
              __half* __restrict__ occ, float* __restrict__ q)
{
    extern __shared__ __align__(16) char smem[];
    float* W2s = (float*)(smem + W2OFF);   // [64][132]
    float* W3s = (float*)(smem + W3OFF);   // [64][68]
    float* H1s = (float*)(smem + H1OFF);   // [32][132]
    float* H2s = (float*)(smem + H2OFF);   // [64][132]

    const int t = threadIdx.x;
    const int s0 = blockIdx.x * 128, b = blockIdx.z;
    const int tm = t >> 4, tn = t & 15;    // 16 x 16

#pragma unroll
    for (int i = 0; i < 8; ++i) {
        const int vid = t + i * 256;
        const int r = vid >> 5, c4 = (vid & 31) * 4;
        *(float4*)&W2s[r * 132 + c4] = *(const float4*)(wo2 + r * 128 + c4);
    }
#pragma unroll
    for (int i = 0; i < 4; ++i) {
        const int vid = t + i * 256;
        const int r = vid >> 4, c4 = (vid & 15) * 4;
        *(float4*)&W3s[r * 68 + c4] = *(const float4*)(wo3 + r * 64 + c4);
    }

    float acc1[4][8];
#pragma unroll
    for (int i = 0; i < 4; ++i)
#pragma unroll
        for (int j = 0; j < 8; ++j) acc1[i][j] = 0.f;

    for (int c0 = 0; c0 < 128; c0 += 32) {
        __syncthreads();
#pragma unroll
        for (int i = 0; i < 4; ++i) {
            const int vid = t + i * 256;
            const int r = vid >> 5, sc = (vid & 31) * 4;
            H4 u;
            u.u = *(const uint2*)(h1 + ((long)b * 128 + c0 + r) * SS + s0 + sc);
            H1s[r * 132 + sc + 0] = __half2float(u.h[0]);
            H1s[r * 132 + sc + 1] = __half2float(u.h[1]);
            H1s[r * 132 + sc + 2] = __half2float(u.h[2]);
            H1s[r * 132 + sc + 3] = __half2float(u.h[3]);
        }
        __syncthreads();
#pragma unroll
        for (int kk = 0; kk < 32; ++kk) {
            float a[4], v[8];
#pragma unroll
            for (int i = 0; i < 4; ++i) a[i] = W2s[(tm * 4 + i) * 132 + c0 + kk];
#pragma unroll
            for (int j = 0; j < 8; ++j) v[j] = H1s[kk * 132 + tn * 8 + j];
#pragma unroll
            for (int i = 0; i < 4; ++i)
#pragma unroll
                for (int j = 0; j < 8; ++j) acc1[i][j] += a[i] * v[j];
        }
    }
    __syncthreads();
#pragma unroll
    for (int i = 0; i < 4; ++i) {
        const float bv = bo2[tm * 4 + i];
#pragma unroll
        for (int j = 0; j < 8; ++j)
            H2s[(tm * 4 + i) * 132 + tn * 8 + j] = fmaxf(acc1[i][j] + bv, 0.f);
    }
    __syncthreads();

    float acc2[4][8];
#pragma unroll
    for (int i = 0; i < 4; ++i)
#pragma unroll
        for (int j = 0; j < 8; ++j) acc2[i][j] = 0.f;
#pragma unroll
    for (int kk = 0; kk < 64; ++kk) {
        float a[4], v[8];
#pragma unroll
        for (int i = 0; i < 4; ++i) a[i] = W3s[(tm * 4 + i) * 68 + kk];
#pragma unroll
        for (int j = 0; j < 8; ++j) v[j] = H2s[kk * 132 + tn * 8 + j];
#pragma unroll
        for (int i = 0; i < 4; ++i)
#pragma unroll
            for (int j = 0; j < 8; ++j) acc2[i][j] += a[i] * v[j];
    }
#pragma unroll
    for (int i = 0; i < 4; ++i) {
        const int o = tm * 4 + i;
        float av[8];
        float qp = 0.f;
        H8 ov;
#pragma unroll
        for (int j = 0; j < 8; ++j) {
            av[j] = fabsf(acc2[i][j]);
            qp += av[j];
            ov.h[j] = __float2half(av[j]);
        }
        *(uint4*)(occ + ((long)b * COUT + o) * SS + s0 + tn * 8) = ov.u;
#pragma unroll
        for (int off = 8; off > 0; off >>= 1)
            qp += __shfl_xor_sync(0xffffffff, qp, off);
        if (tn == 0) atomicAdd(&q[b * COUT + o], qp * (1.0f / (float)SS));
    }
}

// ------ P[b,o,k] = (1/S) sum_s occ[b,o,s] * y1[b,k,s]  (split-K atomics) ------
__global__ __launch_bounds__(256)
void pool_contract(const __half* __restrict__ Occ, const __half* __restrict__ Y1,
                   float* __restrict__ P)
{
    const int S = SS;
    const int bz = blockIdx.z;
    const int b  = bz / NSPLIT;
    const int sp = bz % NSPLIT;
    const int chunk = S / NSPLIT;
    const int sbeg  = sp * chunk;

    const __half* Ab = Occ + (long)b * COUT * S;
    const __half* Fb = Y1  + (long)b * CIN  * S;
    const int n0 = blockIdx.x * 64;

    __shared__ float As[16][64 + 4];
    __shared__ float Bs[16][64 + 4];

    const int t  = threadIdx.x;
    const int tn = t % 16;
    const int tm = t / 16;
    const int lrow = t >> 2;
    const int lk   = (t & 3) * 4;

    float acc[4][4];
#pragma unroll
    for (int i = 0; i < 4; i++)
#pragma unroll
        for (int j = 0; j < 4; j++) acc[i][j] = 0.f;

    for (int s0 = sbeg; s0 < sbeg + chunk; s0 += 16) {
        H4 a4, f4;
        a4.u = *(const uint2*)(Ab + (long)lrow * S + s0 + lk);
        As[lk+0][lrow] = __half2float(a4.h[0]);
        As[lk+1][lrow] = __half2float(a4.h[1]);
        As[lk+2][lrow] = __half2float(a4.h[2]);
        As[lk+3][lrow] = __half2float(a4.h[3]);
        f4.u = *(const uint2*)(Fb + (long)(n0 + lrow) * S + s0 + lk);
        Bs[lk+0][lrow] = __half2float(f4.h[0]);
        Bs[lk+1][lrow] = __half2float(f4.h[1]);
        Bs[lk+2][lrow] = __half2float(f4.h[2]);
        Bs[lk+3][lrow] = __half2float(f4.h[3]);
        __syncthreads();

#pragma unroll
        for (int kk = 0; kk < 16; kk++) {
            float4 av = *(const float4*)&As[kk][tm * 4];
            float4 bv = *(const float4*)&Bs[kk][tn * 4];
            float a[4] = {av.x, av.y, av.z, av.w};
            float c[4] = {bv.x, bv.y, bv.z, bv.w};
#pragma unroll
            for (int i = 0; i < 4; i++)
#pragma unroll
                for (int j = 0; j < 4; j++) acc[i][j] += a[i] * c[j];
        }
        __syncthreads();
    }

    const float scale = 1.0f / (float)S;
#pragma unroll
    for (int i = 0; i < 4; i++)
#pragma unroll
        for (int j = 0; j < 4; j++) {
            const int o = tm * 4 + i;
            const int k = n0 + tn * 4 + j;
            atomicAdd(&P[((long)b * COUT + o) * CIN + k], acc[i][j] * scale);
        }
}

// ------ out[b,o,c] = sum_k P[b,o,k]*W2[c,k] + q[b,o]*b2[c] -------------------
__global__ __launch_bounds__(256)
void fin_gemm(const float* __restrict__ P, const float* __restrict__ q,
              const float* __restrict__ W2, const float* __restrict__ b2,
              float* __restrict__ out)
{
    const int b = blockIdx.z, c0 = blockIdx.x * 64;
    __shared__ float Pt[64][68];
    __shared__ float Wt[64][68];
    const int t = threadIdx.x;
    const int tm = t >> 4, tn = t & 15;

    float acc[4][4];
#pragma unroll
    for (int i = 0; i < 4; i++)
#pragma unroll
        for (int j = 0; j < 4; j++) acc[i][j] = 0.f;

    for (int k0 = 0; k0 < CIN; k0 += 64) {
#pragma unroll
        for (int i = 0; i < 4; ++i) {
            const int r  = (t >> 4) + i * 16;
            const int kc = (t & 15) * 4;
            *(float4*)&Pt[r][kc] = *(const float4*)(P + ((long)b * COUT + r) * CIN + k0 + kc);
            *(float4*)&Wt[r][kc] = *(const float4*)(W2 + (long)(c0 + r) * CIN + k0 + kc);
        }
        __syncthreads();
#pragma unroll
        for (int kk = 0; kk < 64; ++kk) {
            float a[4], w[4];
#pragma unroll
            for (int i = 0; i < 4; ++i) a[i] = Pt[tm * 4 + i][kk];
#pragma unroll
            for (int j = 0; j < 4; ++j) w[j] = Wt[tn * 4 + j][kk];
#pragma unroll
            for (int i = 0; i < 4; ++i)
#pragma unroll
                for (int j = 0; j < 4; ++j) acc[i][j] += a[i] * w[j];
        }
        __syncthreads();
    }

#pragma unroll
    for (int i = 0; i < 4; ++i) {
        const int o = tm * 4 + i;
        const float qv = q[b * COUT + o];
#pragma unroll
        for (int j = 0; j < 4; ++j) {
            const int c = c0 + tn * 4 + j;
            out[((long)b * COUT + o) * CIN + c] = acc[i][j] + qv * b2[c];
        }
    }
}

// -----------------------------------------------------------------------------
extern "C" void kernel_launch(void* const* d_in, const int* in_sizes, int n_in,
                              void* d_out, int out_size)
{
    const float* x      = (const float*)d_in[0];
    const float* w_add1 = (const float*)d_in[1];
    const float* b_add1 = (const float*)d_in[2];
    const float* w_add2 = (const float*)d_in[3];
    const float* b_add2 = (const float*)d_in[4];
    const float* w_occ1 = (const float*)d_in[5];
    const float* b_occ1 = (const float*)d_in[6];
    const float* w_occ2 = (const float*)d_in[7];
    const float* b_occ2 = (const float*)d_in[8];
    const float* w_occ3 = (const float*)d_in[9];
    float* out = (float*)d_out;

    __half *xth, *xtl, *wch, *y1, *h1, *occ;
    float *P, *q, *bc;
    cudaGetSymbolAddress((void**)&xth, g_xt_hi);
    cudaGetSymbolAddress((void**)&xtl, g_xt_lo);
    cudaGetSymbolAddress((void**)&y1,  g_y1);
    cudaGetSymbolAddress((void**)&h1,  g_h1);
    cudaGetSymbolAddress((void**)&occ, g_occ);
    cudaGetSymbolAddress((void**)&P,   g_P);
    cudaGetSymbolAddress((void**)&q,   g_q);
    cudaGetSymbolAddress((void**)&wch, g_wch);
    cudaGetSymbolAddress((void**)&bc,  g_bc);

    cudaFuncSetAttribute(hmma_gemm, cudaFuncAttributeMaxDynamicSharedMemorySize, HSMEM);
    cudaFuncSetAttribute(occ_tail,  cudaFuncAttributeMaxDynamicSharedMemorySize, OSMEM);

    // launches #1-#3 (pre), #4 = hmma_gemm (ncu captures launch #4)
    transpose_split<<<dim3(SS/32, CIN/32, NB), dim3(32, 8)>>>(x, xth, xtl);
    wsplit_all<<<(MTOT*CIN + 255) / 256, 256>>>(w_add1, w_occ1, wch);
    prep<<<(NB*COUT*CIN + 255) / 256, 256>>>(b_add1, b_occ1, bc, P, q);

    // merged add1 + occ1: rows 0..511 -> y1 fp16, rows 512..639 -> h1 fp16
    hmma_gemm<<<dim3(SS/128, MTOT/128, NB), 128, HSMEM>>>(wch, xth, xtl, bc, y1, h1);

    // fused occ tail (occ2 + occ3 + q), fp16 in/out
    occ_tail<<<dim3(SS/128, 1, NB), 256, OSMEM>>>(h1, w_occ2, b_occ2, w_occ3, occ, q);

    // P = (1/S) occ . y1^T (fp16 inputs, fp32 accum)
    pool_contract<<<dim3(CIN/64, 1, NB * NSPLIT), 256>>>(occ, y1, P);

    // out = P . W2^T + q b2^T
    fin_gemm<<<dim3(CIN/64, 1, NB), 256>>>(P, q, w_add2, b_add2, out);
}

// round 14
// speedup vs baseline: 1.7493x; 1.2223x over previous
#include <cuda_runtime.h>
#include <cuda_fp16.h>
#include <mma.h>
#include <cstdint>

using namespace nvcuda;

#define NB   4
#define CIN  512
#define COUT 64
#define SS   16384   // T*H*W
#define PSPLIT 32
#define MTOT 640     // 512 (add1) + 128 (occ1) fused rows

// ---------------- scratch (device globals; no allocs allowed) ----------------
__device__ __half g_y1 [(size_t)NB * CIN * SS];     // relu(add1) fp16 (B,512,S)
__device__ __half g_h1 [(size_t)NB * 128 * SS];     // relu(occ1)  fp16
__device__ __half g_occ[(size_t)NB *  64 * SS];     // |occ3|      fp16
__device__ float g_P   [(size_t)NB * COUT * CIN];
__device__ float g_q   [(size_t)NB * COUT];
__device__ __half g_wch[MTOT * CIN];                // concat W rows, fp16
__device__ float g_bc[MTOT];                        // concat bias

// ---------------- helpers ----------------------------------------------------
__device__ __forceinline__ uint32_t smem_u32(const void* p) {
    uint32_t a;
    asm("{ .reg .u64 t; cvta.to.shared.u64 t, %1; cvt.u32.u64 %0, t; }" : "=r"(a) : "l"(p));
    return a;
}
__device__ __forceinline__ void cp16(uint32_t dst, const void* src) {
    asm volatile("cp.async.cg.shared.global [%0], [%1], 16;" :: "r"(dst), "l"(src));
}
__device__ __forceinline__ void cp_commit() {
    asm volatile("cp.async.commit_group;" ::: "memory");
}
template<int N>
__device__ __forceinline__ void cp_wait() {
    asm volatile("cp.async.wait_group %0;" :: "n"(N) : "memory");
}
union H4 { uint2 u; __half h[4]; };
union H8 { uint4 u; __half h[8]; };

// ---------------- pre-passes (3 launches so hmma_gemm is launch #4) ----------
__global__ void wsplit_all(const float* __restrict__ W1, const float* __restrict__ Wo1,
                           __half* __restrict__ H)
{
    int i = blockIdx.x * 256 + threadIdx.x;
    if (i >= MTOT * CIN) return;
    float v = (i < 512 * CIN) ? W1[i] : Wo1[i - 512 * CIN];
    H[i] = __float2half(v);
}

__global__ void prep_bias(const float* __restrict__ b1, const float* __restrict__ bo1,
                          float* __restrict__ bc, float* __restrict__ q)
{
    int i = blockIdx.x * 256 + threadIdx.x;
    if (i < NB * COUT) q[i] = 0.f;
    if (i < 512) bc[i] = b1[i];
    else if (i < MTOT) bc[i] = bo1[i - 512];
}

__global__ void zero_P(float* __restrict__ P)
{
    int i = blockIdx.x * 256 + threadIdx.x;
    if (i < NB * COUT * CIN) P[i] = 0.f;
}

// ---------------- merged HMMA GEMM: direct-x fp16 2-term, 128 thr ------------
// D(128x128) = Wc(640,512) x X(512,S) tile. W fp16 via cp.async; X fp32 ->
// REGS (coalesced, natively (k=c, n=s) row-major) -> fp16 hi/lo split ->
// row-major B tiles. 2-term: W*Xh + W*Xl (fp32 accum).
// rows m0<512 -> y1 fp16; rows m0>=512 -> h1 fp16. bias+relu.
// smem/stage: W 10240 | Bh 8704 (32x136) | Bl 8704 = 27648, x2 = 55296.
#define STG   27648
#define BH_O  10240
#define BL_O  18944
#define HSMEM 67584     // epilogue Dsm 128x132x4 dominates
__global__ __launch_bounds__(128)
void hmma_gemm(const __half* __restrict__ Wh, const float* __restrict__ X,
               const float* __restrict__ bias,
               __half* __restrict__ Y1, __half* __restrict__ H1)
{
    extern __shared__ __align__(128) char smem[];
    const int t = threadIdx.x, wid = t >> 5;
    const int n0 = blockIdx.x * 128, m0 = blockIdx.y * 128, b = blockIdx.z;
    const uint32_t sb = smem_u32(smem);

    const int wm = wid & 1;        // 2 warp rows -> 64 m each
    const int wn = wid >> 1;       // 2 warp cols -> 64 n each

    const __half* wh = Wh + (long)m0 * 512;
    const float*  xb = X + (long)b * CIN * SS + n0;

    const int kq    = t >> 2;            // 0..31 (k-row within chunk)
    const int nsegF = (t & 3) * 32;      // 0,32,64,96 (n offset, floats)

    auto cpW = [&](int c, int st) {
        const int k0 = c * 32;
#pragma unroll
        for (int i = 0; i < 4; ++i) {
            const int vid = t + i * 128;
            const int r = vid >> 2, v = vid & 3;
            cp16(sb + st * STG + r * 80 + v * 16, wh + (long)r * 512 + k0 + v * 8);
        }
        cp_commit();
    };

    float4 xv[8];
    auto ldgX = [&](int c) {
        const float* src = xb + (long)(c * 32 + kq) * SS + nsegF;
#pragma unroll
        for (int g = 0; g < 8; ++g) xv[g] = *(const float4*)(src + g * 4);
    };
    auto convert = [&](int st) {
        __half* Bh = (__half*)(smem + st * STG + BH_O) + kq * 136 + nsegF;
        __half* Bl = (__half*)(smem + st * STG + BL_O) + kq * 136 + nsegF;
        const float* xf = (const float*)xv;
#pragma unroll
        for (int g = 0; g < 4; ++g) {
            H8 hh, hl;
#pragma unroll
            for (int e = 0; e < 8; ++e) {
                float v = xf[g * 8 + e];
                __half h = __float2half(v);
                hh.h[e] = h;
                hl.h[e] = __float2half(v - __half2float(h));
            }
            *(uint4*)(Bh + g * 8) = hh.u;
            *(uint4*)(Bl + g * 8) = hl.u;
        }
    };

    wmma::fragment<wmma::accumulator, 16, 16, 16, float> acc[4][4];
#pragma unroll
    for (int i = 0; i < 4; ++i)
#pragma unroll
        for (int j = 0; j < 4; ++j) wmma::fill_fragment(acc[i][j], 0.0f);

    ldgX(0);
    cpW(0, 0);

    for (int c = 0; c < 16; ++c) {
        const int st = c & 1, nx = st ^ 1;
        cp_wait<0>();              // W(c) landed (this thread's group)
        convert(st);               // own regs -> B(st); prior readers done at barrier(c-1)
        __syncthreads();           // W(st)+B(st) visible; MMA(c-1) complete
        if (c + 1 < 16) { ldgX(c + 1); cpW(c + 1, nx); }

        const __half* Ah  = (const __half*)(smem + st * STG);
        const __half* Bhs = (const __half*)(smem + st * STG + BH_O);
        const __half* Bls = (const __half*)(smem + st * STG + BL_O);

#pragma unroll
        for (int kk = 0; kk < 32; kk += 16) {
            wmma::fragment<wmma::matrix_a, 16, 16, 16, __half, wmma::row_major> fah[4];
#pragma unroll
            for (int i = 0; i < 4; ++i)
                wmma::load_matrix_sync(fah[i], Ah + (wm * 64 + i * 16) * 40 + kk, 40);
#pragma unroll
            for (int j = 0; j < 4; ++j) {
                wmma::fragment<wmma::matrix_b, 16, 16, 16, __half, wmma::row_major> fbh, fbl;
                wmma::load_matrix_sync(fbh, Bhs + kk * 136 + wn * 64 + j * 16, 136);
                wmma::load_matrix_sync(fbl, Bls + kk * 136 + wn * 64 + j * 16, 136);
#pragma unroll
                for (int i = 0; i < 4; ++i) {
                    wmma::mma_sync(acc[i][j], fah[i], fbh, acc[i][j]);
                    wmma::mma_sync(acc[i][j], fah[i], fbl, acc[i][j]);
                }
            }
        }
    }
    __syncthreads();               // last MMA reads done before Dsm reuse

    // ---- epilogue: bias + relu, fp16 output, routed ----
    float* Dsm = (float*)smem;    // [m][n] 128 x 132
#pragma unroll
    for (int i = 0; i < 4; ++i)
#pragma unroll
        for (int j = 0; j < 4; ++j)
            wmma::store_matrix_sync(Dsm + (wm * 64 + i * 16) * 132 + wn * 64 + j * 16,
                                    acc[i][j], 132, wmma::mem_row_major);
    __syncthreads();
    const int r = t;
    const float bv = bias[m0 + r];
    __half* yr = (m0 < 512)
               ? Y1 + ((long)b * CIN + m0 + r) * SS + n0
               : H1 + ((long)b * 128 + (m0 - 512) + r) * SS + n0;
#pragma unroll
    for (int j = 0; j < 128; j += 8) {
        H8 o;
#pragma unroll
        for (int e = 0; e < 8; ++e)
            o.h[e] = __float2half(fmaxf(Dsm[r * 132 + j + e] + bv, 0.f));
        *(uint4*)(yr + j) = o.u;
    }
}

// -------- fused occ tail: h2 = relu(Wo2 h1 + b), occ = |Wo3 h2|, q += sums ----
#define W2OFF 0
#define W3OFF 33792
#define H1OFF 51200
#define H2OFF 68096
#define OSMEM 101888
__global__ __launch_bounds__(256)
void occ_tail(const __half* __restrict__ h1, const float* __restrict__ wo2,
              const float* __restrict__ bo2, const float* __restrict__ wo3,
              __half* __restrict__ occ, float* __restrict__ q)
{
    extern __shared__ __align__(16) char smem[];
    float* W2s = (float*)(smem + W2OFF);   // [64][132]
    float* W3s = (float*)(smem + W3OFF);   // [64][68]
    float* H1s = (float*)(smem + H1OFF);   // [32][132]
    float* H2s = (float*)(smem + H2OFF);   // [64][132]

    const int t = threadIdx.x;
    const int s0 = blockIdx.x * 128, b = blockIdx.z;
    const int tm = t >> 4, tn = t & 15;    // 16 x 16

#pragma unroll
    for (int i = 0; i < 8; ++i) {
        const int vid = t + i * 256;
        const int r = vid >> 5, c4 = (vid & 31) * 4;
        *(float4*)&W2s[r * 132 + c4] = *(const float4*)(wo2 + r * 128 + c4);
    }
#pragma unroll
    for (int i = 0; i < 4; ++i) {
        const int vid = t + i * 256;
        const int r = vid >> 4, c4 = (vid & 15) * 4;
        *(float4*)&W3s[r * 68 + c4] = *(const float4*)(wo3 + r * 64 + c4);
    }

    float acc1[4][8];
#pragma unroll
    for (int i = 0; i < 4; ++i)
#pragma unroll
        for (int j = 0; j < 8; ++j) acc1[i][j] = 0.f;

    for (int c0 = 0; c0 < 128; c0 += 32) {
        __syncthreads();
#pragma unroll
        for (int i = 0; i < 4; ++i) {
            const int vid = t + i * 256;
            const int r = vid >> 5, sc = (vid & 31) * 4;
            H4 u;
            u.u = *(const uint2*)(h1 + ((long)b * 128 + c0 + r) * SS + s0 + sc);
            H1s[r * 132 + sc + 0] = __half2float(u.h[0]);
            H1s[r * 132 + sc + 1] = __half2float(u.h[1]);
            H1s[r * 132 + sc + 2] = __half2float(u.h[2]);
            H1s[r * 132 + sc + 3] = __half2float(u.h[3]);
        }
        __syncthreads();
#pragma unroll
        for (int kk = 0; kk < 32; ++kk) {
            float a[4], v[8];
#pragma unroll
            for (int i = 0; i < 4; ++i) a[i] = W2s[(tm * 4 + i) * 132 + c0 + kk];
#pragma unroll
            for (int j = 0; j < 8; ++j) v[j] = H1s[kk * 132 + tn * 8 + j];
#pragma unroll
            for (int i = 0; i < 4; ++i)
#pragma unroll
                for (int j = 0; j < 8; ++j) acc1[i][j] += a[i] * v[j];
        }
    }
    __syncthreads();
#pragma unroll
    for (int i = 0; i < 4; ++i) {
        const float bv = bo2[tm * 4 + i];
#pragma unroll
        for (int j = 0; j < 8; ++j)
            H2s[(tm * 4 + i) * 132 + tn * 8 + j] = fmaxf(acc1[i][j] + bv, 0.f);
    }
    __syncthreads();

    float acc2[4][8];
#pragma unroll
    for (int i = 0; i < 4; ++i)
#pragma unroll
        for (int j = 0; j < 8; ++j) acc2[i][j] = 0.f;
#pragma unroll
    for (int kk = 0; kk < 64; ++kk) {
        float a[4], v[8];
#pragma unroll
        for (int i = 0; i < 4; ++i) a[i] = W3s[(tm * 4 + i) * 68 + kk];
#pragma unroll
        for (int j = 0; j < 8; ++j) v[j] = H2s[kk * 132 + tn * 8 + j];
#pragma unroll
        for (int i = 0; i < 4; ++i)
#pragma unroll
            for (int j = 0; j < 8; ++j) acc2[i][j] += a[i] * v[j];
    }
#pragma unroll
    for (int i = 0; i < 4; ++i) {
        const int o = tm * 4 + i;
        float av[8];
        float qp = 0.f;
        H8 ov;
#pragma unroll
        for (int j = 0; j < 8; ++j) {
            av[j] = fabsf(acc2[i][j]);
            qp += av[j];
            ov.h[j] = __float2half(av[j]);
        }
        *(uint4*)(occ + ((long)b * COUT + o) * SS + s0 + tn * 8) = ov.u;
#pragma unroll
        for (int off = 8; off > 0; off >>= 1)
            qp += __shfl_xor_sync(0xffffffff, qp, off);
        if (tn == 0) atomicAdd(&q[b * COUT + o], qp * (1.0f / (float)SS));
    }
}

// ------ P[b,o,k] = (1/S) sum_s occ*y1 — TENSOR-CORE version -------------------
// occ (64 o, s) fp16 = matrix_a row_major; y1 rows (cin, s) fp16 = matrix_b
// col_major (k=s contiguous). Split-K over s, fp32 atomics into P.
__global__ __launch_bounds__(128)
void pool_tc(const __half* __restrict__ Occ, const __half* __restrict__ Y1,
             float* __restrict__ P)
{
    __shared__ __half As[64 * 72];
    __shared__ __half Bs[64 * 72];
    __shared__ float Dsm[64 * 68];

    const int bz = blockIdx.z;
    const int b  = bz / PSPLIT;
    const int sp = bz % PSPLIT;
    const int sbeg = sp * (SS / PSPLIT);    // 512-s chunk
    const int c0 = blockIdx.x * 64;
    const int t = threadIdx.x, wid = t >> 5;
    const int wo = wid & 1, wc = wid >> 1;  // 2x2 warp grid, 32o x 32cin each

    const __half* Ab = Occ + (long)b * COUT * SS;
    const __half* Fb = Y1  + (long)b * CIN  * SS;

    wmma::fragment<wmma::accumulator, 16, 16, 16, float> acc[2][2];
#pragma unroll
    for (int i = 0; i < 2; ++i)
#pragma unroll
        for (int j = 0; j < 2; ++j) wmma::fill_fragment(acc[i][j], 0.0f);

    for (int s0 = sbeg; s0 < sbeg + SS / PSPLIT; s0 += 64) {
        __syncthreads();                    // prior tile reads done
#pragma unroll
        for (int i = 0; i < 4; ++i) {
            const int vid = t + i * 128;
            const int r = vid >> 3, sg = (vid & 7) * 8;
            *(uint4*)&As[r * 72 + sg] = *(const uint4*)(Ab + (long)r * SS + s0 + sg);
            *(uint4*)&Bs[r * 72 + sg] = *(const uint4*)(Fb + (long)(c0 + r) * SS + s0 + sg);
        }
        __syncthreads();
#pragma unroll
        for (int kk = 0; kk < 64; kk += 16) {
            wmma::fragment<wmma::matrix_a, 16, 16, 16, __half, wmma::row_major> fa[2];
            wmma::fragment<wmma::matrix_b, 16, 16, 16, __half, wmma::col_major> fb[2];
#pragma unroll
            for (int i = 0; i < 2; ++i)
                wmma::load_matrix_sync(fa[i], As + (wo * 32 + i * 16) * 72 + kk, 72);
#pragma unroll
            for (int j = 0; j < 2; ++j)
                wmma::load_matrix_sync(fb[j], Bs + (wc * 32 + j * 16) * 72 + kk, 72);
#pragma unroll
            for (int i = 0; i < 2; ++i)
#pragma unroll
                for (int j = 0; j < 2; ++j)
                    wmma::mma_sync(acc[i][j], fa[i], fb[j], acc[i][j]);
        }
    }
    __syncthreads();
#pragma unroll
    for (int i = 0; i < 2; ++i)
#pragma unroll
        for (int j = 0; j < 2; ++j)
            wmma::store_matrix_sync(Dsm + (wo * 32 + i * 16) * 68 + wc * 32 + j * 16,
                                    acc[i][j], 68, wmma::mem_row_major);
    __syncthreads();
    const float scale = 1.0f / (float)SS;
#pragma unroll
    for (int i = 0; i < 32; ++i) {
        const int idx = t + i * 128;        // 0..4095
        const int o = idx >> 6, c = idx & 63;
        atomicAdd(&P[((long)b * COUT + o) * CIN + c0 + c], Dsm[o * 68 + c] * scale);
    }
}

// ------ out[b,o,c] = sum_k P[b,o,k]*W2[c,k] + q[b,o]*b2[c] -------------------
__global__ __launch_bounds__(256)
void fin_gemm(const float* __restrict__ P, const float* __restrict__ q,
              const float* __restrict__ W2, const float* __restrict__ b2,
              float* __restrict__ out)
{
    const int b = blockIdx.z, c0 = blockIdx.x * 64;
    __shared__ float Pt[64][68];
    __shared__ float Wt[64][68];
    const int t = threadIdx.x;
    const int tm = t >> 4, tn = t & 15;

    float acc[4][4];
#pragma unroll
    for (int i = 0; i < 4; i++)
#pragma unroll
        for (int j = 0; j < 4; j++) acc[i][j] = 0.f;

    for (int k0 = 0; k0 < CIN; k0 += 64) {
#pragma unroll
        for (int i = 0; i < 4; ++i) {
            const int r  = (t >> 4) + i * 16;
            const int kc = (t & 15) * 4;
            *(float4*)&Pt[r][kc] = *(const float4*)(P + ((long)b * COUT + r) * CIN + k0 + kc);
            *(float4*)&Wt[r][kc] = *(const float4*)(W2 + (long)(c0 + r) * CIN + k0 + kc);
        }
        __syncthreads();
#pragma unroll
        for (int kk = 0; kk < 64; ++kk) {
            float a[4], w[4];
#pragma unroll
            for (int i = 0; i < 4; ++i) a[i] = Pt[tm * 4 + i][kk];
#pragma unroll
            for (int j = 0; j < 4; ++j) w[j] = Wt[tn * 4 + j][kk];
#pragma unroll
            for (int i = 0; i < 4; ++i)
#pragma unroll
                for (int j = 0; j < 4; ++j) acc[i][j] += a[i] * w[j];
        }
        __syncthreads();
    }

#pragma unroll
    for (int i = 0; i < 4; ++i) {
        const int o = tm * 4 + i;
        const float qv = q[b * COUT + o];
#pragma unroll
        for (int j = 0; j < 4; ++j) {
            const int c = c0 + tn * 4 + j;
            out[((long)b * COUT + o) * CIN + c] = acc[i][j] + qv * b2[c];
        }
    }
}

// -----------------------------------------------------------------------------
extern "C" void kernel_launch(void* const* d_in, const int* in_sizes, int n_in,
                              void* d_out, int out_size)
{
    const float* x      = (const float*)d_in[0];
    const float* w_add1 = (const float*)d_in[1];
    const float* b_add1 = (const float*)d_in[2];
    const float* w_add2 = (const float*)d_in[3];
    const float* b_add2 = (const float*)d_in[4];
    const float* w_occ1 = (const float*)d_in[5];
    const float* b_occ1 = (const float*)d_in[6];
    const float* w_occ2 = (const float*)d_in[7];
    const float* b_occ2 = (const float*)d_in[8];
    const float* w_occ3 = (const float*)d_in[9];
    float* out = (float*)d_out;

    __half *wch, *y1, *h1, *occ;
    float *P, *q, *bc;
    cudaGetSymbolAddress((void**)&y1,  g_y1);
    cudaGetSymbolAddress((void**)&h1,  g_h1);
    cudaGetSymbolAddress((void**)&occ, g_occ);
    cudaGetSymbolAddress((void**)&P,   g_P);
    cudaGetSymbolAddress((void**)&q,   g_q);
    cudaGetSymbolAddress((void**)&wch, g_wch);
    cudaGetSymbolAddress((void**)&bc,  g_bc);

    cudaFuncSetAttribute(hmma_gemm, cudaFuncAttributeMaxDynamicSharedMemorySize, HSMEM);
    cudaFuncSetAttribute(occ_tail,  cudaFuncAttributeMaxDynamicSharedMemorySize, OSMEM);

    // launches #1-#3 (pre), #4 = hmma_gemm (ncu captures launch #4)
    wsplit_all<<<(MTOT*CIN + 255) / 256, 256>>>(w_add1, w_occ1, wch);
    prep_bias<<<(MTOT + 255) / 256, 256>>>(b_add1, b_occ1, bc, q);
    zero_P<<<(NB*COUT*CIN + 255) / 256, 256>>>(P);

    // merged add1 + occ1, x consumed directly (no transpose pre-pass)
    hmma_gemm<<<dim3(SS/128, MTOT/128, NB), 128, HSMEM>>>(wch, x, bc, y1, h1);

    // fused occ tail (occ2 + occ3 + q), fp16 in/out
    occ_tail<<<dim3(SS/128, 1, NB), 256, OSMEM>>>(h1, w_occ2, b_occ2, w_occ3, occ, q);

    // P = (1/S) occ . y1^T  (tensor cores, fp16 in / fp32 accum)
    pool_tc<<<dim3(CIN/64, 1, NB * PSPLIT), 128>>>(occ, y1, P);

    // out = P . W2^T + q b2^T
    fin_gemm<<<dim3(CIN/64, 1, NB), 256>>>(P, q, w_add2, b_add2, out);
}

// round 15
// speedup vs baseline: 1.9483x; 1.1137x over previous
#include <cuda_runtime.h>
#include <cuda_fp16.h>
#include <mma.h>
#include <cstdint>

using namespace nvcuda;

#define NB   4
#define CIN  512
#define COUT 64
#define SS   16384   // T*H*W
#define PSPLIT 32
#define MTOT 640     // 512 (add1) + 128 (occ1) fused rows

// ---------------- scratch (device globals; no allocs allowed) ----------------
__device__ __half g_y1 [(size_t)NB * CIN * SS];     // relu(add1) fp16 (B,512,S)
__device__ __half g_h1 [(size_t)NB * 128 * SS];     // relu(occ1)  fp16
__device__ __half g_occ[(size_t)NB *  64 * SS];     // |occ3|      fp16
__device__ float g_P   [(size_t)NB * COUT * CIN];
__device__ float g_q   [(size_t)NB * COUT];
__device__ __half g_wch[MTOT * CIN];                // concat W rows, fp16
__device__ float g_bc[MTOT];                        // concat bias

// ---------------- helpers ----------------------------------------------------
__device__ __forceinline__ uint32_t smem_u32(const void* p) {
    uint32_t a;
    asm("{ .reg .u64 t; cvta.to.shared.u64 t, %1; cvt.u32.u64 %0, t; }" : "=r"(a) : "l"(p));
    return a;
}
__device__ __forceinline__ void cp16(uint32_t dst, const void* src) {
    asm volatile("cp.async.cg.shared.global [%0], [%1], 16;" :: "r"(dst), "l"(src));
}
__device__ __forceinline__ void cp_commit() {
    asm volatile("cp.async.commit_group;" ::: "memory");
}
template<int N>
__device__ __forceinline__ void cp_wait() {
    asm volatile("cp.async.wait_group %0;" :: "n"(N) : "memory");
}
union H4 { uint2 u; __half h[4]; };
union H8 { uint4 u; __half h[8]; };

// ---------------- pre-passes (3 launches so hmma_gemm is launch #4) ----------
__global__ void wsplit_all(const float* __restrict__ W1, const float* __restrict__ Wo1,
                           __half* __restrict__ H)
{
    int i = blockIdx.x * 256 + threadIdx.x;
    if (i >= MTOT * CIN) return;
    float v = (i < 512 * CIN) ? W1[i] : Wo1[i - 512 * CIN];
    H[i] = __float2half(v);
}

__global__ void prep_bias(const float* __restrict__ b1, const float* __restrict__ bo1,
                          float* __restrict__ bc, float* __restrict__ q)
{
    int i = blockIdx.x * 256 + threadIdx.x;
    if (i < NB * COUT) q[i] = 0.f;
    if (i < 512) bc[i] = b1[i];
    else if (i < MTOT) bc[i] = bo1[i - 512];
}

__global__ void zero_P(float* __restrict__ P)
{
    int i = blockIdx.x * 256 + threadIdx.x;
    if (i < NB * COUT * CIN) P[i] = 0.f;
}

// ---------------- merged HMMA GEMM: direct-x fp16 1-term, 128 thr ------------
// D(128x128) = Wc(640,512) x X(512,S) tile. W fp16 via cp.async; X fp32 ->
// REGS (coalesced, natively (k=c, n=s) row-major) -> fp16 -> row-major B tile.
// Single-term W*Xh (fp32 accum): X/W fp16 rounding residuals average down by
// ~sqrt(S) in the final mean-pool (R12-calibrated error model).
// rows m0<512 -> y1 fp16; rows m0>=512 -> h1 fp16. bias+relu.
// smem/stage: W 10240 | Bh 8704 (32x136) = 18944, x2 = 37888.
#define STG   18944
#define BH_O  10240
#define HSMEM 67584     // epilogue Dsm 128x132x4 dominates
__global__ __launch_bounds__(128)
void hmma_gemm(const __half* __restrict__ Wh, const float* __restrict__ X,
               const float* __restrict__ bias,
               __half* __restrict__ Y1, __half* __restrict__ H1)
{
    extern __shared__ __align__(128) char smem[];
    const int t = threadIdx.x, wid = t >> 5;
    const int n0 = blockIdx.x * 128, m0 = blockIdx.y * 128, b = blockIdx.z;
    const uint32_t sb = smem_u32(smem);

    const int wm = wid & 1;        // 2 warp rows -> 64 m each
    const int wn = wid >> 1;       // 2 warp cols -> 64 n each

    const __half* wh = Wh + (long)m0 * 512;
    const float*  xb = X + (long)b * CIN * SS + n0;

    const int kq    = t >> 2;            // 0..31 (k-row within chunk)
    const int nsegF = (t & 3) * 32;      // 0,32,64,96 (n offset, floats)

    auto cpW = [&](int c, int st) {
        const int k0 = c * 32;
#pragma unroll
        for (int i = 0; i < 4; ++i) {
            const int vid = t + i * 128;
            const int r = vid >> 2, v = vid & 3;
            cp16(sb + st * STG + r * 80 + v * 16, wh + (long)r * 512 + k0 + v * 8);
        }
        cp_commit();
    };

    float4 xv[8];
    auto ldgX = [&](int c) {
        const float* src = xb + (long)(c * 32 + kq) * SS + nsegF;
#pragma unroll
        for (int g = 0; g < 8; ++g) xv[g] = *(const float4*)(src + g * 4);
    };
    auto convert = [&](int st) {
        __half* Bh = (__half*)(smem + st * STG + BH_O) + kq * 136 + nsegF;
        const float* xf = (const float*)xv;
#pragma unroll
        for (int g = 0; g < 4; ++g) {
            H8 hh;
#pragma unroll
            for (int e = 0; e < 8; ++e)
                hh.h[e] = __float2half(xf[g * 8 + e]);
            *(uint4*)(Bh + g * 8) = hh.u;
        }
    };

    wmma::fragment<wmma::accumulator, 16, 16, 16, float> acc[4][4];
#pragma unroll
    for (int i = 0; i < 4; ++i)
#pragma unroll
        for (int j = 0; j < 4; ++j) wmma::fill_fragment(acc[i][j], 0.0f);

    ldgX(0);
    cpW(0, 0);

    for (int c = 0; c < 16; ++c) {
        const int st = c & 1, nx = st ^ 1;
        cp_wait<0>();              // W(c) landed (this thread's group)
        convert(st);               // own regs -> B(st); prior readers done at barrier(c-1)
        __syncthreads();           // W(st)+B(st) visible; MMA(c-1) complete
        if (c + 1 < 16) { ldgX(c + 1); cpW(c + 1, nx); }

        const __half* Ah  = (const __half*)(smem + st * STG);
        const __half* Bhs = (const __half*)(smem + st * STG + BH_O);

#pragma unroll
        for (int kk = 0; kk < 32; kk += 16) {
            wmma::fragment<wmma::matrix_a, 16, 16, 16, __half, wmma::row_major> fah[4];
#pragma unroll
            for (int i = 0; i < 4; ++i)
                wmma::load_matrix_sync(fah[i], Ah + (wm * 64 + i * 16) * 40 + kk, 40);
#pragma unroll
            for (int j = 0; j < 4; ++j) {
                wmma::fragment<wmma::matrix_b, 16, 16, 16, __half, wmma::row_major> fbh;
                wmma::load_matrix_sync(fbh, Bhs + kk * 136 + wn * 64 + j * 16, 136);
#pragma unroll
                for (int i = 0; i < 4; ++i)
                    wmma::mma_sync(acc[i][j], fah[i], fbh, acc[i][j]);
            }
        }
    }
    __syncthreads();               // last MMA reads done before Dsm reuse

    // ---- epilogue: bias + relu, fp16 output, routed ----
    float* Dsm = (float*)smem;    // [m][n] 128 x 132
#pragma unroll
    for (int i = 0; i < 4; ++i)
#pragma unroll
        for (int j = 0; j < 4; ++j)
            wmma::store_matrix_sync(Dsm + (wm * 64 + i * 16) * 132 + wn * 64 + j * 16,
                                    acc[i][j], 132, wmma::mem_row_major);
    __syncthreads();
    const int r = t;
    const float bv = bias[m0 + r];
    __half* yr = (m0 < 512)
               ? Y1 + ((long)b * CIN + m0 + r) * SS + n0
               : H1 + ((long)b * 128 + (m0 - 512) + r) * SS + n0;
#pragma unroll
    for (int j = 0; j < 128; j += 8) {
        H8 o;
#pragma unroll
        for (int e = 0; e < 8; ++e)
            o.h[e] = __float2half(fmaxf(Dsm[r * 132 + j + e] + bv, 0.f));
        *(uint4*)(yr + j) = o.u;
    }
}

// -------- fused occ tail: h2 = relu(Wo2 h1 + b), occ = |Wo3 h2|, q += sums ----
#define W2OFF 0
#define W3OFF 33792
#define H1OFF 51200
#define H2OFF 68096
#define OSMEM 101888
__global__ __launch_bounds__(256)
void occ_tail(const __half* __restrict__ h1, const float* __restrict__ wo2,
              const float* __restrict__ bo2, const float* __restrict__ wo3,
              __half* __restrict__ occ, float* __restrict__ q)
{
    extern __shared__ __align__(16) char smem[];
    float* W2s = (float*)(smem + W2OFF);   // [64][132]
    float* W3s = (float*)(smem + W3OFF);   // [64][68]
    float* H1s = (float*)(smem + H1OFF);   // [32][132]
    float* H2s = (float*)(smem + H2OFF);   // [64][132]

    const int t = threadIdx.x;
    const int s0 = blockIdx.x * 128, b = blockIdx.z;
    const int tm = t >> 4, tn = t & 15;    // 16 x 16

#pragma unroll
    for (int i = 0; i < 8; ++i) {
        const int vid = t + i * 256;
        const int r = vid >> 5, c4 = (vid & 31) * 4;
        *(float4*)&W2s[r * 132 + c4] = *(const float4*)(wo2 + r * 128 + c4);
    }
#pragma unroll
    for (int i = 0; i < 4; ++i) {
        const int vid = t + i * 256;
        const int r = vid >> 4, c4 = (vid & 15) * 4;
        *(float4*)&W3s[r * 68 + c4] = *(const float4*)(wo3 + r * 64 + c4);
    }

    float acc1[4][8];
#pragma unroll
    for (int i = 0; i < 4; ++i)
#pragma unroll
        for (int j = 0; j < 8; ++j) acc1[i][j] = 0.f;

    for (int c0 = 0; c0 < 128; c0 += 32) {
        __syncthreads();
#pragma unroll
        for (int i = 0; i < 4; ++i) {
            const int vid = t + i * 256;
            const int r = vid >> 5, sc = (vid & 31) * 4;
            H4 u;
            u.u = *(const uint2*)(h1 + ((long)b * 128 + c0 + r) * SS + s0 + sc);
            H1s[r * 132 + sc + 0] = __half2float(u.h[0]);
            H1s[r * 132 + sc + 1] = __half2float(u.h[1]);
            H1s[r * 132 + sc + 2] = __half2float(u.h[2]);
            H1s[r * 132 + sc + 3] = __half2float(u.h[3]);
        }
        __syncthreads();
#pragma unroll
        for (int kk = 0; kk < 32; ++kk) {
            float a[4], v[8];
#pragma unroll
            for (int i = 0; i < 4; ++i) a[i] = W2s[(tm * 4 + i) * 132 + c0 + kk];
#pragma unroll
            for (int j = 0; j < 8; ++j) v[j] = H1s[kk * 132 + tn * 8 + j];
#pragma unroll
            for (int i = 0; i < 4; ++i)
#pragma unroll
                for (int j = 0; j < 8; ++j) acc1[i][j] += a[i] * v[j];
        }
    }
    __syncthreads();
#pragma unroll
    for (int i = 0; i < 4; ++i) {
        const float bv = bo2[tm * 4 + i];
#pragma unroll
        for (int j = 0; j < 8; ++j)
            H2s[(tm * 4 + i) * 132 + tn * 8 + j] = fmaxf(acc1[i][j] + bv, 0.f);
    }
    __syncthreads();

    float acc2[4][8];
#pragma unroll
    for (int i = 0; i < 4; ++i)
#pragma unroll
        for (int j = 0; j < 8; ++j) acc2[i][j] = 0.f;
#pragma unroll
    for (int kk = 0; kk < 64; ++kk) {
        float a[4], v[8];
#pragma unroll
        for (int i = 0; i < 4; ++i) a[i] = W3s[(tm * 4 + i) * 68 + kk];
#pragma unroll
        for (int j = 0; j < 8; ++j) v[j] = H2s[kk * 132 + tn * 8 + j];
#pragma unroll
        for (int i = 0; i < 4; ++i)
#pragma unroll
            for (int j = 0; j < 8; ++j) acc2[i][j] += a[i] * v[j];
    }
#pragma unroll
    for (int i = 0; i < 4; ++i) {
        const int o = tm * 4 + i;
        float av[8];
        float qp = 0.f;
        H8 ov;
#pragma unroll
        for (int j = 0; j < 8; ++j) {
            av[j] = fabsf(acc2[i][j]);
            qp += av[j];
            ov.h[j] = __float2half(av[j]);
        }
        *(uint4*)(occ + ((long)b * COUT + o) * SS + s0 + tn * 8) = ov.u;
#pragma unroll
        for (int off = 8; off > 0; off >>= 1)
            qp += __shfl_xor_sync(0xffffffff, qp, off);
        if (tn == 0) atomicAdd(&q[b * COUT + o], qp * (1.0f / (float)SS));
    }
}

// ------ P[b,o,k] = (1/S) sum_s occ*y1 — tensor-core split-K ------------------
__global__ __launch_bounds__(128)
void pool_tc(const __half* __restrict__ Occ, const __half* __restrict__ Y1,
             float* __restrict__ P)
{
    __shared__ __half As[64 * 72];
    __shared__ __half Bs[64 * 72];
    __shared__ float Dsm[64 * 68];

    const int bz = blockIdx.z;
    const int b  = bz / PSPLIT;
    const int sp = bz % PSPLIT;
    const int sbeg = sp * (SS / PSPLIT);    // 512-s chunk
    const int c0 = blockIdx.x * 64;
    const int t = threadIdx.x, wid = t >> 5;
    const int wo = wid & 1, wc = wid >> 1;  // 2x2 warp grid, 32o x 32cin each

    const __half* Ab = Occ + (long)b * COUT * SS;
    const __half* Fb = Y1  + (long)b * CIN  * SS;

    wmma::fragment<wmma::accumulator, 16, 16, 16, float> acc[2][2];
#pragma unroll
    for (int i = 0; i < 2; ++i)
#pragma unroll
        for (int j = 0; j < 2; ++j) wmma::fill_fragment(acc[i][j], 0.0f);

    for (int s0 = sbeg; s0 < sbeg + SS / PSPLIT; s0 += 64) {
        __syncthreads();                    // prior tile reads done
#pragma unroll
        for (int i = 0; i < 4; ++i) {
            const int vid = t + i * 128;
            const int r = vid >> 3, sg = (vid & 7) * 8;
            *(uint4*)&As[r * 72 + sg] = *(const uint4*)(Ab + (long)r * SS + s0 + sg);
            *(uint4*)&Bs[r * 72 + sg] = *(const uint4*)(Fb + (long)(c0 + r) * SS + s0 + sg);
        }
        __syncthreads();
#pragma unroll
        for (int kk = 0; kk < 64; kk += 16) {
            wmma::fragment<wmma::matrix_a, 16, 16, 16, __half, wmma::row_major> fa[2];
            wmma::fragment<wmma::matrix_b, 16, 16, 16, __half, wmma::col_major> fb[2];
#pragma unroll
            for (int i = 0; i < 2; ++i)
                wmma::load_matrix_sync(fa[i], As + (wo * 32 + i * 16) * 72 + kk, 72);
#pragma unroll
            for (int j = 0; j < 2; ++j)
                wmma::load_matrix_sync(fb[j], Bs + (wc * 32 + j * 16) * 72 + kk, 72);
#pragma unroll
            for (int i = 0; i < 2; ++i)
#pragma unroll
                for (int j = 0; j < 2; ++j)
                    wmma::mma_sync(acc[i][j], fa[i], fb[j], acc[i][j]);
        }
    }
    __syncthreads();
#pragma unroll
    for (int i = 0; i < 2; ++i)
#pragma unroll
        for (int j = 0; j < 2; ++j)
            wmma::store_matrix_sync(Dsm + (wo * 32 + i * 16) * 68 + wc * 32 + j * 16,
                                    acc[i][j], 68, wmma::mem_row_major);
    __syncthreads();
    const float scale = 1.0f / (float)SS;
#pragma unroll
    for (int i = 0; i < 32; ++i) {
        const int idx = t + i * 128;        // 0..4095
        const int o = idx >> 6, c = idx & 63;
        atomicAdd(&P[((long)b * COUT + o) * CIN + c0 + c], Dsm[o * 68 + c] * scale);
    }
}

// ------ out[b,o,c] = sum_k P[b,o,k]*W2[c,k] + q[b,o]*b2[c] -------------------
__global__ __launch_bounds__(256)
void fin_gemm(const float* __restrict__ P, const float* __restrict__ q,
              const float* __restrict__ W2, const float* __restrict__ b2,
              float* __restrict__ out)
{
    const int b = blockIdx.z, c0 = blockIdx.x * 64;
    __shared__ float Pt[64][68];
    __shared__ float Wt[64][68];
    const int t = threadIdx.x;
    const int tm = t >> 4, tn = t & 15;

    float acc[4][4];
#pragma unroll
    for (int i = 0; i < 4; i++)
#pragma unroll
        for (int j = 0; j < 4; j++) acc[i][j] = 0.f;

    for (int k0 = 0; k0 < CIN; k0 += 64) {
#pragma unroll
        for (int i = 0; i < 4; ++i) {
            const int r  = (t >> 4) + i * 16;
            const int kc = (t & 15) * 4;
            *(float4*)&Pt[r][kc] = *(const float4*)(P + ((long)b * COUT + r) * CIN + k0 + kc);
            *(float4*)&Wt[r][kc] = *(const float4*)(W2 + (long)(c0 + r) * CIN + k0 + kc);
        }
        __syncthreads();
#pragma unroll
        for (int kk = 0; kk < 64; ++kk) {
            float a[4], w[4];
#pragma unroll
            for (int i = 0; i < 4; ++i) a[i] = Pt[tm * 4 + i][kk];
#pragma unroll
            for (int j = 0; j < 4; ++j) w[j] = Wt[tn * 4 + j][kk];
#pragma unroll
            for (int i = 0; i < 4; ++i)
#pragma unroll
                for (int j = 0; j < 4; ++j) acc[i][j] += a[i] * w[j];
        }
        __syncthreads();
    }

#pragma unroll
    for (int i = 0; i < 4; ++i) {
        const int o = tm * 4 + i;
        const float qv = q[b * COUT + o];
#pragma unroll
        for (int j = 0; j < 4; ++j) {
            const int c = c0 + tn * 4 + j;
            out[((long)b * COUT + o) * CIN + c] = acc[i][j] + qv * b2[c];
        }
    }
}

// -----------------------------------------------------------------------------
extern "C" void kernel_launch(void* const* d_in, const int* in_sizes, int n_in,
                              void* d_out, int out_size)
{
    const float* x      = (const float*)d_in[0];
    const float* w_add1 = (const float*)d_in[1];
    const float* b_add1 = (const float*)d_in[2];
    const float* w_add2 = (const float*)d_in[3];
    const float* b_add2 = (const float*)d_in[4];
    const float* w_occ1 = (const float*)d_in[5];
    const float* b_occ1 = (const float*)d_in[6];
    const float* w_occ2 = (const float*)d_in[7];
    const float* b_occ2 = (const float*)d_in[8];
    const float* w_occ3 = (const float*)d_in[9];
    float* out = (float*)d_out;

    __half *wch, *y1, *h1, *occ;
    float *P, *q, *bc;
    cudaGetSymbolAddress((void**)&y1,  g_y1);
    cudaGetSymbolAddress((void**)&h1,  g_h1);
    cudaGetSymbolAddress((void**)&occ, g_occ);
    cudaGetSymbolAddress((void**)&P,   g_P);
    cudaGetSymbolAddress((void**)&q,   g_q);
    cudaGetSymbolAddress((void**)&wch, g_wch);
    cudaGetSymbolAddress((void**)&bc,  g_bc);

    cudaFuncSetAttribute(hmma_gemm, cudaFuncAttributeMaxDynamicSharedMemorySize, HSMEM);
    cudaFuncSetAttribute(occ_tail,  cudaFuncAttributeMaxDynamicSharedMemorySize, OSMEM);

    // launches #1-#3 (pre), #4 = hmma_gemm (ncu captures launch #4)
    wsplit_all<<<(MTOT*CIN + 255) / 256, 256>>>(w_add1, w_occ1, wch);
    prep_bias<<<(MTOT + 255) / 256, 256>>>(b_add1, b_occ1, bc, q);
    zero_P<<<(NB*COUT*CIN + 255) / 256, 256>>>(P);

    // merged add1 + occ1, x consumed directly, 1-term fp16
    hmma_gemm<<<dim3(SS/128, MTOT/128, NB), 128, HSMEM>>>(wch, x, bc, y1, h1);

    // fused occ tail (occ2 + occ3 + q), fp16 in/out
    occ_tail<<<dim3(SS/128, 1, NB), 256, OSMEM>>>(h1, w_occ2, b_occ2, w_occ3, occ, q);

    // P = (1/S) occ . y1^T  (tensor cores, fp16 in / fp32 accum)
    pool_tc<<<dim3(CIN/64, 1, NB * PSPLIT), 128>>>(occ, y1, P);

    // out = P . W2^T + q b2^T
    fin_gemm<<<dim3(CIN/64, 1, NB), 256>>>(P, q, w_add2, b_add2, out);
}

// round 16
// speedup vs baseline: 2.4180x; 1.2411x over previous
#include <cuda_runtime.h>
#include <cuda_fp16.h>
#include <mma.h>
#include <cstdint>

using namespace nvcuda;

#define NB   4
#define CIN  512
#define COUT 64
#define SS   16384   // T*H*W
#define PSPLIT 32
#define MTOT 640     // 512 (add1) + 128 (occ1) fused rows

// ---------------- scratch (device globals; no allocs allowed) ----------------
__device__ __half g_xh [(size_t)NB * CIN * SS];     // x fp16, (B,C,S) layout
__device__ __half g_y1 [(size_t)NB * CIN * SS];     // relu(add1) fp16 (B,512,S)
__device__ __half g_h1 [(size_t)NB * 128 * SS];     // relu(occ1)  fp16
__device__ __half g_occ[(size_t)NB *  64 * SS];     // |occ3|      fp16
__device__ float g_P   [(size_t)NB * COUT * CIN];
__device__ float g_q   [(size_t)NB * COUT];
__device__ __half g_wch[MTOT * CIN];                // concat W rows, fp16
__device__ float g_bc[MTOT];                        // concat bias

// ---------------- helpers ----------------------------------------------------
__device__ __forceinline__ uint32_t smem_u32(const void* p) {
    uint32_t a;
    asm("{ .reg .u64 t; cvta.to.shared.u64 t, %1; cvt.u32.u64 %0, t; }" : "=r"(a) : "l"(p));
    return a;
}
__device__ __forceinline__ void cp16(uint32_t dst, const void* src) {
    asm volatile("cp.async.cg.shared.global [%0], [%1], 16;" :: "r"(dst), "l"(src));
}
__device__ __forceinline__ void cp_commit() {
    asm volatile("cp.async.commit_group;" ::: "memory");
}
template<int N>
__device__ __forceinline__ void cp_wait() {
    asm volatile("cp.async.wait_group %0;" :: "n"(N) : "memory");
}
union H4 { uint2 u; __half h[4]; };
union H8 { uint4 u; __half h[8]; };

// ---------------- pre-passes (3 launches so hmma_gemm is launch #4) ----------
// x fp32 -> fp16, same (B,C,S) layout. One shot; hmma then cp.asyncs it 5x.
__global__ __launch_bounds__(256)
void xcast(const float* __restrict__ X, __half* __restrict__ Xh)
{
    const long i = ((long)blockIdx.x * 256 + threadIdx.x) * 8;
    float4 a = *(const float4*)(X + i);
    float4 c = *(const float4*)(X + i + 4);
    H8 o;
    o.h[0] = __float2half(a.x); o.h[1] = __float2half(a.y);
    o.h[2] = __float2half(a.z); o.h[3] = __float2half(a.w);
    o.h[4] = __float2half(c.x); o.h[5] = __float2half(c.y);
    o.h[6] = __float2half(c.z); o.h[7] = __float2half(c.w);
    *(uint4*)(Xh + i) = o.u;
}

__global__ void wsplit_all(const float* __restrict__ W1, const float* __restrict__ Wo1,
                           __half* __restrict__ H)
{
    int i = blockIdx.x * 256 + threadIdx.x;
    if (i >= MTOT * CIN) return;
    float v = (i < 512 * CIN) ? W1[i] : Wo1[i - 512 * CIN];
    H[i] = __float2half(v);
}

// zero P + zero q + bias concat, one launch
__global__ void prep(const float* __restrict__ b1, const float* __restrict__ bo1,
                     float* __restrict__ bc, float* __restrict__ P, float* __restrict__ q)
{
    int i = blockIdx.x * 256 + threadIdx.x;
    if (i < NB * COUT * CIN) P[i] = 0.f;
    if (i < NB * COUT) q[i] = 0.f;
    if (i < 512) bc[i] = b1[i];
    else if (i < MTOT) bc[i] = bo1[i - 512];
}

// ---------------- merged HMMA GEMM: all-cp.async fp16 1-term, 128 thr --------
// D(128x128) = Wc(640,512) x Xh(512,S) tile. Both operands fp16 via cp.async;
// no in-kernel convert, no LDG staging. rows m0<512 -> y1; else h1. bias+relu.
// smem/stage: W 10240 (128m x 80B) | B 8704 (32k x 272B) = 18944, x2 = 37888.
#define STG   18944
#define BH_O  10240
#define HSMEM 67584     // epilogue Dsm 128x132x4 dominates
__global__ __launch_bounds__(128)
void hmma_gemm(const __half* __restrict__ Wh, const __half* __restrict__ Xh,
               const float* __restrict__ bias,
               __half* __restrict__ Y1, __half* __restrict__ H1)
{
    extern __shared__ __align__(128) char smem[];
    const int t = threadIdx.x, wid = t >> 5;
    const int n0 = blockIdx.x * 128, m0 = blockIdx.y * 128, b = blockIdx.z;
    const uint32_t sb = smem_u32(smem);

    const int wm = wid & 1;        // 2 warp rows -> 64 m each
    const int wn = wid >> 1;       // 2 warp cols -> 64 n each

    const __half* wh = Wh + (long)m0 * 512;
    const __half* xb = Xh + (long)b * CIN * SS + n0;

    auto cpWB = [&](int c, int st) {
        const int k0 = c * 32;
        // W tile: 128 m-rows x 32 k fp16 (64B) at r*80
#pragma unroll
        for (int i = 0; i < 4; ++i) {
            const int vid = t + i * 128;
            const int r = vid >> 2, v = vid & 3;
            cp16(sb + st * STG + r * 80 + v * 16, wh + (long)r * 512 + k0 + v * 8);
        }
        // B tile: 32 k-rows x 128 n fp16 (256B) at r*272 (ld 136 halves)
#pragma unroll
        for (int i = 0; i < 4; ++i) {
            const int vid = t + i * 128;
            const int r = vid >> 4, v = vid & 15;
            cp16(sb + st * STG + BH_O + r * 272 + v * 16,
                 xb + (long)(k0 + r) * SS + v * 8);
        }
        cp_commit();
    };

    wmma::fragment<wmma::accumulator, 16, 16, 16, float> acc[4][4];
#pragma unroll
    for (int i = 0; i < 4; ++i)
#pragma unroll
        for (int j = 0; j < 4; ++j) wmma::fill_fragment(acc[i][j], 0.0f);

    cpWB(0, 0);

    for (int c = 0; c < 16; ++c) {
        const int st = c & 1, nx = st ^ 1;
        cp_wait<0>();              // chunk c landed (this thread's groups)
        __syncthreads();           // visibility + stage-nx readers (iter c-1) done
        if (c + 1 < 16) cpWB(c + 1, nx);   // flies under MMA(c)

        const __half* Ah  = (const __half*)(smem + st * STG);
        const __half* Bhs = (const __half*)(smem + st * STG + BH_O);

#pragma unroll
        for (int kk = 0; kk < 32; kk += 16) {
            wmma::fragment<wmma::matrix_a, 16, 16, 16, __half, wmma::row_major> fah[4];
#pragma unroll
            for (int i = 0; i < 4; ++i)
                wmma::load_matrix_sync(fah[i], Ah + (wm * 64 + i * 16) * 40 + kk, 40);
#pragma unroll
            for (int j = 0; j < 4; ++j) {
                wmma::fragment<wmma::matrix_b, 16, 16, 16, __half, wmma::row_major> fbh;
                wmma::load_matrix_sync(fbh, Bhs + kk * 136 + wn * 64 + j * 16, 136);
#pragma unroll
                for (int i = 0; i < 4; ++i)
                    wmma::mma_sync(acc[i][j], fah[i], fbh, acc[i][j]);
            }
        }
    }
    __syncthreads();               // last MMA reads done before Dsm reuse

    // ---- epilogue: bias + relu, fp16 output, routed ----
    float* Dsm = (float*)smem;    // [m][n] 128 x 132
#pragma unroll
    for (int i = 0; i < 4; ++i)
#pragma unroll
        for (int j = 0; j < 4; ++j)
            wmma::store_matrix_sync(Dsm + (wm * 64 + i * 16) * 132 + wn * 64 + j * 16,
                                    acc[i][j], 132, wmma::mem_row_major);
    __syncthreads();
    const int r = t;
    const float bv = bias[m0 + r];
    __half* yr = (m0 < 512)
               ? Y1 + ((long)b * CIN + m0 + r) * SS + n0
               : H1 + ((long)b * 128 + (m0 - 512) + r) * SS + n0;
#pragma unroll
    for (int j = 0; j < 128; j += 8) {
        H8 o;
#pragma unroll
        for (int e = 0; e < 8; ++e)
            o.h[e] = __float2half(fmaxf(Dsm[r * 132 + j + e] + bv, 0.f));
        *(uint4*)(yr + j) = o.u;
    }
}

// -------- fused occ tail: h2 = relu(Wo2 h1 + b), occ = |Wo3 h2|, q += sums ----
#define W2OFF 0
#define W3OFF 33792
#define H1OFF 51200
#define H2OFF 68096
#define OSMEM 101888
__global__ __launch_bounds__(256)
void occ_tail(const __half* __restrict__ h1, const float* __restrict__ wo2,
              const float* __restrict__ bo2, const float* __restrict__ wo3,
              __half* __restrict__ occ, float* __restrict__ q)
{
    extern __shared__ __align__(16) char smem[];
    float* W2s = (float*)(smem + W2OFF);   // [64][132]
    float* W3s = (float*)(smem + W3OFF);   // [64][68]
    float* H1s = (float*)(smem + H1OFF);   // [32][132]
    float* H2s = (float*)(smem + H2OFF);   // [64][132]

    const int t = threadIdx.x;
    const int s0 = blockIdx.x * 128, b = blockIdx.z;
    const int tm = t >> 4, tn = t & 15;    // 16 x 16

#pragma unroll
    for (int i = 0; i < 8; ++i) {
        const int vid = t + i * 256;
        const int r = vid >> 5, c4 = (vid & 31) * 4;
        *(float4*)&W2s[r * 132 + c4] = *(const float4*)(wo2 + r * 128 + c4);
    }
#pragma unroll
    for (int i = 0; i < 4; ++i) {
        const int vid = t + i * 256;
        const int r = vid >> 4, c4 = (vid & 15) * 4;
        *(float4*)&W3s[r * 68 + c4] = *(const float4*)(wo3 + r * 64 + c4);
    }

    float acc1[4][8];
#pragma unroll
    for (int i = 0; i < 4; ++i)
#pragma unroll
        for (int j = 0; j < 8; ++j) acc1[i][j] = 0.f;

    for (int c0 = 0; c0 < 128; c0 += 32) {
        __syncthreads();
#pragma unroll
        for (int i = 0; i < 4; ++i) {
            const int vid = t + i * 256;
            const int r = vid >> 5, sc = (vid & 31) * 4;
            H4 u;
            u.u = *(const uint2*)(h1 + ((long)b * 128 + c0 + r) * SS + s0 + sc);
            H1s[r * 132 + sc + 0] = __half2float(u.h[0]);
            H1s[r * 132 + sc + 1] = __half2float(u.h[1]);
            H1s[r * 132 + sc + 2] = __half2float(u.h[2]);
            H1s[r * 132 + sc + 3] = __half2float(u.h[3]);
        }
        __syncthreads();
#pragma unroll
        for (int kk = 0; kk < 32; ++kk) {
            float a[4], v[8];
#pragma unroll
            for (int i = 0; i < 4; ++i) a[i] = W2s[(tm * 4 + i) * 132 + c0 + kk];
#pragma unroll
            for (int j = 0; j < 8; ++j) v[j] = H1s[kk * 132 + tn * 8 + j];
#pragma unroll
            for (int i = 0; i < 4; ++i)
#pragma unroll
                for (int j = 0; j < 8; ++j) acc1[i][j] += a[i] * v[j];
        }
    }
    __syncthreads();
#pragma unroll
    for (int i = 0; i < 4; ++i) {
        const float bv = bo2[tm * 4 + i];
#pragma unroll
        for (int j = 0; j < 8; ++j)
            H2s[(tm * 4 + i) * 132 + tn * 8 + j] = fmaxf(acc1[i][j] + bv, 0.f);
    }
    __syncthreads();

    float acc2[4][8];
#pragma unroll
    for (int i = 0; i < 4; ++i)
#pragma unroll
        for (int j = 0; j < 8; ++j) acc2[i][j] = 0.f;
#pragma unroll
    for (int kk = 0; kk < 64; ++kk) {
        float a[4], v[8];
#pragma unroll
        for (int i = 0; i < 4; ++i) a[i] = W3s[(tm * 4 + i) * 68 + kk];
#pragma unroll
        for (int j = 0; j < 8; ++j) v[j] = H2s[kk * 132 + tn * 8 + j];
#pragma unroll
        for (int i = 0; i < 4; ++i)
#pragma unroll
            for (int j = 0; j < 8; ++j) acc2[i][j] += a[i] * v[j];
    }
#pragma unroll
    for (int i = 0; i < 4; ++i) {
        const int o = tm * 4 + i;
        float av[8];
        float qp = 0.f;
        H8 ov;
#pragma unroll
        for (int j = 0; j < 8; ++j) {
            av[j] = fabsf(acc2[i][j]);
            qp += av[j];
            ov.h[j] = __float2half(av[j]);
        }
        *(uint4*)(occ + ((long)b * COUT + o) * SS + s0 + tn * 8) = ov.u;
#pragma unroll
        for (int off = 8; off > 0; off >>= 1)
            qp += __shfl_xor_sync(0xffffffff, qp, off);
        if (tn == 0) atomicAdd(&q[b * COUT + o], qp * (1.0f / (float)SS));
    }
}

// ------ P[b,o,k] = (1/S) sum_s occ*y1 — tensor-core split-K ------------------
__global__ __launch_bounds__(128)
void pool_tc(const __half* __restrict__ Occ, const __half* __restrict__ Y1,
             float* __restrict__ P)
{
    __shared__ __half As[64 * 72];
    __shared__ __half Bs[64 * 72];
    __shared__ float Dsm[64 * 68];

    const int bz = blockIdx.z;
    const int b  = bz / PSPLIT;
    const int sp = bz % PSPLIT;
    const int sbeg = sp * (SS / PSPLIT);    // 512-s chunk
    const int c0 = blockIdx.x * 64;
    const int t = threadIdx.x, wid = t >> 5;
    const int wo = wid & 1, wc = wid >> 1;  // 2x2 warp grid, 32o x 32cin each

    const __half* Ab = Occ + (long)b * COUT * SS;
    const __half* Fb = Y1  + (long)b * CIN  * SS;

    wmma::fragment<wmma::accumulator, 16, 16, 16, float> acc[2][2];
#pragma unroll
    for (int i = 0; i < 2; ++i)
#pragma unroll
        for (int j = 0; j < 2; ++j) wmma::fill_fragment(acc[i][j], 0.0f);

    for (int s0 = sbeg; s0 < sbeg + SS / PSPLIT; s0 += 64) {
        __syncthreads();                    // prior tile reads done
#pragma unroll
        for (int i = 0; i < 4; ++i) {
            const int vid = t + i * 128;
            const int r = vid >> 3, sg = (vid & 7) * 8;
            *(uint4*)&As[r * 72 + sg] = *(const uint4*)(Ab + (long)r * SS + s0 + sg);
            *(uint4*)&Bs[r * 72 + sg] = *(const uint4*)(Fb + (long)(c0 + r) * SS + s0 + sg);
        }
        __syncthreads();
#pragma unroll
        for (int kk = 0; kk < 64; kk += 16) {
            wmma::fragment<wmma::matrix_a, 16, 16, 16, __half, wmma::row_major> fa[2];
            wmma::fragment<wmma::matrix_b, 16, 16, 16, __half, wmma::col_major> fb[2];
#pragma unroll
            for (int i = 0; i < 2; ++i)
                wmma::load_matrix_sync(fa[i], As + (wo * 32 + i * 16) * 72 + kk, 72);
#pragma unroll
            for (int j = 0; j < 2; ++j)
                wmma::load_matrix_sync(fb[j], Bs + (wc * 32 + j * 16) * 72 + kk, 72);
#pragma unroll
            for (int i = 0; i < 2; ++i)
#pragma unroll
                for (int j = 0; j < 2; ++j)
                    wmma::mma_sync(acc[i][j], fa[i], fb[j], acc[i][j]);
        }
    }
    __syncthreads();
#pragma unroll
    for (int i = 0; i < 2; ++i)
#pragma unroll
        for (int j = 0; j < 2; ++j)
            wmma::store_matrix_sync(Dsm + (wo * 32 + i * 16) * 68 + wc * 32 + j * 16,
                                    acc[i][j], 68, wmma::mem_row_major);
    __syncthreads();
    const float scale = 1.0f / (float)SS;
#pragma unroll
    for (int i = 0; i < 32; ++i) {
        const int idx = t + i * 128;        // 0..4095
        const int o = idx >> 6, c = idx & 63;
        atomicAdd(&P[((long)b * COUT + o) * CIN + c0 + c], Dsm[o * 68 + c] * scale);
    }
}

// ------ out[b,o,c] = sum_k P[b,o,k]*W2[c,k] + q[b,o]*b2[c] -------------------
__global__ __launch_bounds__(256)
void fin_gemm(const float* __restrict__ P, const float* __restrict__ q,
              const float* __restrict__ W2, const float* __restrict__ b2,
              float* __restrict__ out)
{
    const int b = blockIdx.z, c0 = blockIdx.x * 64;
    __shared__ float Pt[64][68];
    __shared__ float Wt[64][68];
    const int t = threadIdx.x;
    const int tm = t >> 4, tn = t & 15;

    float acc[4][4];
#pragma unroll
    for (int i = 0; i < 4; i++)
#pragma unroll
        for (int j = 0; j < 4; j++) acc[i][j] = 0.f;

    for (int k0 = 0; k0 < CIN; k0 += 64) {
#pragma unroll
        for (int i = 0; i < 4; ++i) {
            const int r  = (t >> 4) + i * 16;
            const int kc = (t & 15) * 4;
            *(float4*)&Pt[r][kc] = *(const float4*)(P + ((long)b * COUT + r) * CIN + k0 + kc);
            *(float4*)&Wt[r][kc] = *(const float4*)(W2 + (long)(c0 + r) * CIN + k0 + kc);
        }
        __syncthreads();
#pragma unroll
        for (int kk = 0; kk < 64; ++kk) {
            float a[4], w[4];
#pragma unroll
            for (int i = 0; i < 4; ++i) a[i] = Pt[tm * 4 + i][kk];
#pragma unroll
            for (int j = 0; j < 4; ++j) w[j] = Wt[tn * 4 + j][kk];
#pragma unroll
            for (int i = 0; i < 4; ++i)
#pragma unroll
                for (int j = 0; j < 4; ++j) acc[i][j] += a[i] * w[j];
        }
        __syncthreads();
    }

#pragma unroll
    for (int i = 0; i < 4; ++i) {
        const int o = tm * 4 + i;
        const float qv = q[b * COUT + o];
#pragma unroll
        for (int j = 0; j < 4; ++j) {
            const int c = c0 + tn * 4 + j;
            out[((long)b * COUT + o) * CIN + c] = acc[i][j] + qv * b2[c];
        }
    }
}

// -----------------------------------------------------------------------------
extern "C" void kernel_launch(void* const* d_in, const int* in_sizes, int n_in,
                              void* d_out, int out_size)
{
    const float* x      = (const float*)d_in[0];
    const float* w_add1 = (const float*)d_in[1];
    const float* b_add1 = (const float*)d_in[2];
    const float* w_add2 = (const float*)d_in[3];
    const float* b_add2 = (const float*)d_in[4];
    const float* w_occ1 = (const float*)d_in[5];
    const float* b_occ1 = (const float*)d_in[6];
    const float* w_occ2 = (const float*)d_in[7];
    const float* b_occ2 = (const float*)d_in[8];
    const float* w_occ3 = (const float*)d_in[9];
    float* out = (float*)d_out;

    __half *xh, *wch, *y1, *h1, *occ;
    float *P, *q, *bc;
    cudaGetSymbolAddress((void**)&xh,  g_xh);
    cudaGetSymbolAddress((void**)&y1,  g_y1);
    cudaGetSymbolAddress((void**)&h1,  g_h1);
    cudaGetSymbolAddress((void**)&occ, g_occ);
    cudaGetSymbolAddress((void**)&P,   g_P);
    cudaGetSymbolAddress((void**)&q,   g_q);
    cudaGetSymbolAddress((void**)&wch, g_wch);
    cudaGetSymbolAddress((void**)&bc,  g_bc);

    cudaFuncSetAttribute(hmma_gemm, cudaFuncAttributeMaxDynamicSharedMemorySize, HSMEM);
    cudaFuncSetAttribute(occ_tail,  cudaFuncAttributeMaxDynamicSharedMemorySize, OSMEM);

    // launches #1-#3 (pre), #4 = hmma_gemm (ncu captures launch #4)
    xcast<<<(int)(((size_t)NB * CIN * SS) / (256 * 8)), 256>>>(x, xh);
    wsplit_all<<<(MTOT*CIN + 255) / 256, 256>>>(w_add1, w_occ1, wch);
    prep<<<(NB*COUT*CIN + 255) / 256, 256>>>(b_add1, b_occ1, bc, P, q);

    // merged add1 + occ1, all-cp.async fp16 operands
    hmma_gemm<<<dim3(SS/128, MTOT/128, NB), 128, HSMEM>>>(wch, xh, bc, y1, h1);

    // fused occ tail (occ2 + occ3 + q), fp16 in/out
    occ_tail<<<dim3(SS/128, 1, NB), 256, OSMEM>>>(h1, w_occ2, b_occ2, w_occ3, occ, q);

    // P = (1/S) occ . y1^T  (tensor cores, fp16 in / fp32 accum)
    pool_tc<<<dim3(CIN/64, 1, NB * PSPLIT), 128>>>(occ, y1, P);

    // out = P . W2^T + q b2^T
    fin_gemm<<<dim3(CIN/64, 1, NB), 256>>>(P, q, w_add2, b_add2, out);
}

// round 17
// speedup vs baseline: 2.7890x; 1.1534x over previous
#include <cuda_runtime.h>
#include <cuda_fp16.h>
#include <mma.h>
#include <cstdint>

using namespace nvcuda;

#define NB   4
#define CIN  512
#define COUT 64
#define SS   16384   // T*H*W
#define PSPLIT 32
#define MTOT 640     // 512 (add1) + 128 (occ1) fused rows

// ---------------- scratch (device globals; no allocs allowed) ----------------
__device__ __half g_xh [(size_t)NB * CIN * SS];     // x fp16, (B,C,S) layout
__device__ __half g_y1 [(size_t)NB * CIN * SS];     // relu(add1) fp16 (B,512,S)
__device__ __half g_h1 [(size_t)NB * 128 * SS];     // relu(occ1)  fp16
__device__ __half g_occ[(size_t)NB *  64 * SS];     // |occ3|      fp16
__device__ float g_P   [(size_t)NB * COUT * CIN];
__device__ float g_q   [(size_t)NB * COUT];
__device__ __half g_wch[MTOT * CIN];                // concat W rows, fp16
__device__ __half g_w2h[64 * 128];                  // Wo2 fp16
__device__ __half g_w3h[64 * 64];                   // Wo3 fp16
__device__ float g_bc[MTOT];                        // concat bias

// ---------------- helpers ----------------------------------------------------
__device__ __forceinline__ uint32_t smem_u32(const void* p) {
    uint32_t a;
    asm("{ .reg .u64 t; cvta.to.shared.u64 t, %1; cvt.u32.u64 %0, t; }" : "=r"(a) : "l"(p));
    return a;
}
__device__ __forceinline__ void cp16(uint32_t dst, const void* src) {
    asm volatile("cp.async.cg.shared.global [%0], [%1], 16;" :: "r"(dst), "l"(src));
}
__device__ __forceinline__ void cp_commit() {
    asm volatile("cp.async.commit_group;" ::: "memory");
}
template<int N>
__device__ __forceinline__ void cp_wait() {
    asm volatile("cp.async.wait_group %0;" :: "n"(N) : "memory");
}
union H8 { uint4 u; __half h[8]; };

// ---------------- pre-passes (3 launches so hmma_gemm is launch #4) ----------
__global__ __launch_bounds__(256)
void xcast(const float* __restrict__ X, __half* __restrict__ Xh)
{
    const long i = ((long)blockIdx.x * 256 + threadIdx.x) * 8;
    float4 a = *(const float4*)(X + i);
    float4 c = *(const float4*)(X + i + 4);
    H8 o;
    o.h[0] = __float2half(a.x); o.h[1] = __float2half(a.y);
    o.h[2] = __float2half(a.z); o.h[3] = __float2half(a.w);
    o.h[4] = __float2half(c.x); o.h[5] = __float2half(c.y);
    o.h[6] = __float2half(c.z); o.h[7] = __float2half(c.w);
    *(uint4*)(Xh + i) = o.u;
}

__global__ void wsplit_all(const float* __restrict__ W1, const float* __restrict__ Wo1,
                           __half* __restrict__ H)
{
    int i = blockIdx.x * 256 + threadIdx.x;
    if (i >= MTOT * CIN) return;
    float v = (i < 512 * CIN) ? W1[i] : Wo1[i - 512 * CIN];
    H[i] = __float2half(v);
}

// zero P/q + bias concat + Wo2/Wo3 fp16 conversion, one launch
__global__ void prep(const float* __restrict__ b1, const float* __restrict__ bo1,
                     const float* __restrict__ wo2, const float* __restrict__ wo3,
                     float* __restrict__ bc, float* __restrict__ P, float* __restrict__ q,
                     __half* __restrict__ W2h, __half* __restrict__ W3h)
{
    int i = blockIdx.x * 256 + threadIdx.x;
    if (i < NB * COUT * CIN) P[i] = 0.f;
    if (i < NB * COUT) q[i] = 0.f;
    if (i < 512) bc[i] = b1[i];
    else if (i < MTOT) bc[i] = bo1[i - 512];
    if (i < 64 * 128) W2h[i] = __float2half(wo2[i]);
    if (i < 64 * 64)  W3h[i] = __float2half(wo3[i]);
}

// ---------------- merged HMMA GEMM: all-cp.async fp16 1-term, 128 thr --------
#define STG   18944
#define BH_O  10240
#define HSMEM 67584     // epilogue Dsm 128x132x4 dominates
__global__ __launch_bounds__(128)
void hmma_gemm(const __half* __restrict__ Wh, const __half* __restrict__ Xh,
               const float* __restrict__ bias,
               __half* __restrict__ Y1, __half* __restrict__ H1)
{
    extern __shared__ __align__(128) char smem[];
    const int t = threadIdx.x, wid = t >> 5;
    const int n0 = blockIdx.x * 128, m0 = blockIdx.y * 128, b = blockIdx.z;
    const uint32_t sb = smem_u32(smem);

    const int wm = wid & 1;
    const int wn = wid >> 1;

    const __half* wh = Wh + (long)m0 * 512;
    const __half* xb = Xh + (long)b * CIN * SS + n0;

    auto cpWB = [&](int c, int st) {
        const int k0 = c * 32;
#pragma unroll
        for (int i = 0; i < 4; ++i) {
            const int vid = t + i * 128;
            const int r = vid >> 2, v = vid & 3;
            cp16(sb + st * STG + r * 80 + v * 16, wh + (long)r * 512 + k0 + v * 8);
        }
#pragma unroll
        for (int i = 0; i < 4; ++i) {
            const int vid = t + i * 128;
            const int r = vid >> 4, v = vid & 15;
            cp16(sb + st * STG + BH_O + r * 272 + v * 16,
                 xb + (long)(k0 + r) * SS + v * 8);
        }
        cp_commit();
    };

    wmma::fragment<wmma::accumulator, 16, 16, 16, float> acc[4][4];
#pragma unroll
    for (int i = 0; i < 4; ++i)
#pragma unroll
        for (int j = 0; j < 4; ++j) wmma::fill_fragment(acc[i][j], 0.0f);

    cpWB(0, 0);

    for (int c = 0; c < 16; ++c) {
        const int st = c & 1, nx = st ^ 1;
        cp_wait<0>();
        __syncthreads();
        if (c + 1 < 16) cpWB(c + 1, nx);

        const __half* Ah  = (const __half*)(smem + st * STG);
        const __half* Bhs = (const __half*)(smem + st * STG + BH_O);

#pragma unroll
        for (int kk = 0; kk < 32; kk += 16) {
            wmma::fragment<wmma::matrix_a, 16, 16, 16, __half, wmma::row_major> fah[4];
#pragma unroll
            for (int i = 0; i < 4; ++i)
                wmma::load_matrix_sync(fah[i], Ah + (wm * 64 + i * 16) * 40 + kk, 40);
#pragma unroll
            for (int j = 0; j < 4; ++j) {
                wmma::fragment<wmma::matrix_b, 16, 16, 16, __half, wmma::row_major> fbh;
                wmma::load_matrix_sync(fbh, Bhs + kk * 136 + wn * 64 + j * 16, 136);
#pragma unroll
                for (int i = 0; i < 4; ++i)
                    wmma::mma_sync(acc[i][j], fah[i], fbh, acc[i][j]);
            }
        }
    }
    __syncthreads();

    float* Dsm = (float*)smem;    // [m][n] 128 x 132
#pragma unroll
    for (int i = 0; i < 4; ++i)
#pragma unroll
        for (int j = 0; j < 4; ++j)
            wmma::store_matrix_sync(Dsm + (wm * 64 + i * 16) * 132 + wn * 64 + j * 16,
                                    acc[i][j], 132, wmma::mem_row_major);
    __syncthreads();
    const int r = t;
    const float bv = bias[m0 + r];
    __half* yr = (m0 < 512)
               ? Y1 + ((long)b * CIN + m0 + r) * SS + n0
               : H1 + ((long)b * 128 + (m0 - 512) + r) * SS + n0;
#pragma unroll
    for (int j = 0; j < 128; j += 8) {
        H8 o;
#pragma unroll
        for (int e = 0; e < 8; ++e)
            o.h[e] = __float2half(fmaxf(Dsm[r * 132 + j + e] + bv, 0.f));
        *(uint4*)(yr + j) = o.u;
    }
}

// -------- tensor-core occ tail: h2 = relu(Wo2 h1 + b), occ = |Wo3 h2|, q -----
// smem: W2s fp16 64x136 | W3s fp16 64x72 | H1s fp16 128x136 (overlaid by
// Dsm fp32 64x132 after stage-1) | H2s fp16 64x136.
#define TW2  0
#define TW3  17408
#define TH1  26624      // also Dsm (fp32 64x132 = 33792 <= 34816)
#define TH2  61440
#define TSM  78848
__global__ __launch_bounds__(128)
void occ_tail_tc(const __half* __restrict__ h1, const __half* __restrict__ W2h,
                 const float* __restrict__ bo2, const __half* __restrict__ W3h,
                 __half* __restrict__ occ, float* __restrict__ q)
{
    extern __shared__ __align__(128) char smem[];
    __half* W2s = (__half*)(smem + TW2);   // [64][136]
    __half* W3s = (__half*)(smem + TW3);   // [64][72]
    __half* H1s = (__half*)(smem + TH1);   // [128][136]
    float*  Dsm = (float*)(smem + TH1);    // [64][132] (after stage-1 reads)
    __half* H2s = (__half*)(smem + TH2);   // [64][136]

    const int t = threadIdx.x, wid = t >> 5;
    const int s0 = blockIdx.x * 128, b = blockIdx.z;
    const int wo = wid & 1, wn = wid >> 1;  // 2x2 warps: 32o x 64s

    // load weights (fp16)
#pragma unroll
    for (int i = 0; i < 8; ++i) {
        const int vid = t + i * 128;        // 1024 uint4 = 64x128 halves
        const int r = vid >> 4, v = (vid & 15) * 8;
        *(uint4*)&W2s[r * 136 + v] = *(const uint4*)(W2h + r * 128 + v);
    }
#pragma unroll
    for (int i = 0; i < 4; ++i) {
        const int vid = t + i * 128;        // 512 uint4 = 64x64 halves
        const int r = vid >> 3, v = (vid & 7) * 8;
        *(uint4*)&W3s[r * 72 + v] = *(const uint4*)(W3h + r * 64 + v);
    }
    // load h1 tile: 128 c-rows x 128 s fp16
#pragma unroll
    for (int i = 0; i < 16; ++i) {
        const int vid = t + i * 128;
        const int r = vid >> 4, v = (vid & 15) * 8;
        *(uint4*)&H1s[r * 136 + v] = *(const uint4*)(h1 + ((long)b * 128 + r) * SS + s0 + v);
    }
    __syncthreads();

    // stage 1: (64o x 128s) = Wo2 (64x128c) . h1 (128c x 128s)
    wmma::fragment<wmma::accumulator, 16, 16, 16, float> a1[2][4];
#pragma unroll
    for (int i = 0; i < 2; ++i)
#pragma unroll
        for (int j = 0; j < 4; ++j) wmma::fill_fragment(a1[i][j], 0.0f);
#pragma unroll
    for (int kk = 0; kk < 128; kk += 16) {
        wmma::fragment<wmma::matrix_a, 16, 16, 16, __half, wmma::row_major> fa[2];
#pragma unroll
        for (int i = 0; i < 2; ++i)
            wmma::load_matrix_sync(fa[i], W2s + (wo * 32 + i * 16) * 136 + kk, 136);
#pragma unroll
        for (int j = 0; j < 4; ++j) {
            wmma::fragment<wmma::matrix_b, 16, 16, 16, __half, wmma::row_major> fb;
            wmma::load_matrix_sync(fb, H1s + kk * 136 + wn * 64 + j * 16, 136);
#pragma unroll
            for (int i = 0; i < 2; ++i)
                wmma::mma_sync(a1[i][j], fa[i], fb, a1[i][j]);
        }
    }
    __syncthreads();               // H1s reads done -> Dsm may overwrite
#pragma unroll
    for (int i = 0; i < 2; ++i)
#pragma unroll
        for (int j = 0; j < 4; ++j)
            wmma::store_matrix_sync(Dsm + (wo * 32 + i * 16) * 132 + wn * 64 + j * 16,
                                    a1[i][j], 132, wmma::mem_row_major);
    __syncthreads();

    // bias + relu -> H2s fp16 (64 x 136)
#pragma unroll
    for (int i = 0; i < 8; ++i) {
        const int idx = t + i * 128;        // 1024 x 8 elems = 64x128
        const int o = idx >> 4, v = (idx & 15) * 8;
        const float bv = bo2[o];
        H8 hv;
#pragma unroll
        for (int e = 0; e < 8; ++e)
            hv.h[e] = __float2half(fmaxf(Dsm[o * 132 + v + e] + bv, 0.f));
        *(uint4*)&H2s[o * 136 + v] = hv.u;
    }
    __syncthreads();

    // stage 2: (64o x 128s) = Wo3 (64x64c2) . h2 (64c2 x 128s)
    wmma::fragment<wmma::accumulator, 16, 16, 16, float> a2[2][4];
#pragma unroll
    for (int i = 0; i < 2; ++i)
#pragma unroll
        for (int j = 0; j < 4; ++j) wmma::fill_fragment(a2[i][j], 0.0f);
#pragma unroll
    for (int kk = 0; kk < 64; kk += 16) {
        wmma::fragment<wmma::matrix_a, 16, 16, 16, __half, wmma::row_major> fa[2];
#pragma unroll
        for (int i = 0; i < 2; ++i)
            wmma::load_matrix_sync(fa[i], W3s + (wo * 32 + i * 16) * 72 + kk, 72);
#pragma unroll
        for (int j = 0; j < 4; ++j) {
            wmma::fragment<wmma::matrix_b, 16, 16, 16, __half, wmma::row_major> fb;
            wmma::load_matrix_sync(fb, H2s + kk * 136 + wn * 64 + j * 16, 136);
#pragma unroll
            for (int i = 0; i < 2; ++i)
                wmma::mma_sync(a2[i][j], fa[i], fb, a2[i][j]);
        }
    }
    __syncthreads();               // Dsm reads (relu step) long done
#pragma unroll
    for (int i = 0; i < 2; ++i)
#pragma unroll
        for (int j = 0; j < 4; ++j)
            wmma::store_matrix_sync(Dsm + (wo * 32 + i * 16) * 132 + wn * 64 + j * 16,
                                    a2[i][j], 132, wmma::mem_row_major);
    __syncthreads();

    // abs -> occ fp16; q row-sums (8o x 16s thread grid, 8x8 each)
    const int tm = t >> 4, tn = t & 15;    // 8 x 16
#pragma unroll
    for (int i = 0; i < 8; ++i) {
        const int o = tm * 8 + i;
        float qp = 0.f;
        H8 ov;
#pragma unroll
        for (int e = 0; e < 8; ++e) {
            float v = fabsf(Dsm[o * 132 + tn * 8 + e]);
            qp += v;
            ov.h[e] = __float2half(v);
        }
        *(uint4*)(occ + ((long)b * COUT + o) * SS + s0 + tn * 8) = ov.u;
#pragma unroll
        for (int off = 8; off > 0; off >>= 1)
            qp += __shfl_xor_sync(0xffffffff, qp, off);
        if (tn == 0) atomicAdd(&q[b * COUT + o], qp * (1.0f / (float)SS));
    }
}

// ------ P[b,o,k] = (1/S) sum_s occ*y1 — tensor-core split-K ------------------
__global__ __launch_bounds__(128)
void pool_tc(const __half* __restrict__ Occ, const __half* __restrict__ Y1,
             float* __restrict__ P)
{
    __shared__ __half As[64 * 72];
    __shared__ __half Bs[64 * 72];
    __shared__ float Dsm[64 * 68];

    const int bz = blockIdx.z;
    const int b  = bz / PSPLIT;
    const int sp = bz % PSPLIT;
    const int sbeg = sp * (SS / PSPLIT);
    const int c0 = blockIdx.x * 64;
    const int t = threadIdx.x, wid = t >> 5;
    const int wo = wid & 1, wc = wid >> 1;

    const __half* Ab = Occ + (long)b * COUT * SS;
    const __half* Fb = Y1  + (long)b * CIN  * SS;

    wmma::fragment<wmma::accumulator, 16, 16, 16, float> acc[2][2];
#pragma unroll
    for (int i = 0; i < 2; ++i)
#pragma unroll
        for (int j = 0; j < 2; ++j) wmma::fill_fragment(acc[i][j], 0.0f);

    for (int s0 = sbeg; s0 < sbeg + SS / PSPLIT; s0 += 64) {
        __syncthreads();
#pragma unroll
        for (int i = 0; i < 4; ++i) {
            const int vid = t + i * 128;
            const int r = vid >> 3, sg = (vid & 7) * 8;
            *(uint4*)&As[r * 72 + sg] = *(const uint4*)(Ab + (long)r * SS + s0 + sg);
            *(uint4*)&Bs[r * 72 + sg] = *(const uint4*)(Fb + (long)(c0 + r) * SS + s0 + sg);
        }
        __syncthreads();
#pragma unroll
        for (int kk = 0; kk < 64; kk += 16) {
            wmma::fragment<wmma::matrix_a, 16, 16, 16, __half, wmma::row_major> fa[2];
            wmma::fragment<wmma::matrix_b, 16, 16, 16, __half, wmma::col_major> fb[2];
#pragma unroll
            for (int i = 0; i < 2; ++i)
                wmma::load_matrix_sync(fa[i], As + (wo * 32 + i * 16) * 72 + kk, 72);
#pragma unroll
            for (int j = 0; j < 2; ++j)
                wmma::load_matrix_sync(fb[j], Bs + (wc * 32 + j * 16) * 72 + kk, 72);
#pragma unroll
            for (int i = 0; i < 2; ++i)
#pragma unroll
                for (int j = 0; j < 2; ++j)
                    wmma::mma_sync(acc[i][j], fa[i], fb[j], acc[i][j]);
        }
    }
    __syncthreads();
#pragma unroll
    for (int i = 0; i < 2; ++i)
#pragma unroll
        for (int j = 0; j < 2; ++j)
            wmma::store_matrix_sync(Dsm + (wo * 32 + i * 16) * 68 + wc * 32 + j * 16,
                                    acc[i][j], 68, wmma::mem_row_major);
    __syncthreads();
    const float scale = 1.0f / (float)SS;
#pragma unroll
    for (int i = 0; i < 32; ++i) {
        const int idx = t + i * 128;
        const int o = idx >> 6, c = idx & 63;
        atomicAdd(&P[((long)b * COUT + o) * CIN + c0 + c], Dsm[o * 68 + c] * scale);
    }
}

// ------ out[b,o,c] = sum_k P[b,o,k]*W2[c,k] + q[b,o]*b2[c] -------------------
__global__ __launch_bounds__(256)
void fin_gemm(const float* __restrict__ P, const float* __restrict__ q,
              const float* __restrict__ W2, const float* __restrict__ b2,
              float* __restrict__ out)
{
    const int b = blockIdx.z, c0 = blockIdx.x * 64;
    __shared__ float Pt[64][68];
    __shared__ float Wt[64][68];
    const int t = threadIdx.x;
    const int tm = t >> 4, tn = t & 15;

    float acc[4][4];
#pragma unroll
    for (int i = 0; i < 4; i++)
#pragma unroll
        for (int j = 0; j < 4; j++) acc[i][j] = 0.f;

    for (int k0 = 0; k0 < CIN; k0 += 64) {
#pragma unroll
        for (int i = 0; i < 4; ++i) {
            const int r  = (t >> 4) + i * 16;
            const int kc = (t & 15) * 4;
            *(float4*)&Pt[r][kc] = *(const float4*)(P + ((long)b * COUT + r) * CIN + k0 + kc);
            *(float4*)&Wt[r][kc] = *(const float4*)(W2 + (long)(c0 + r) * CIN + k0 + kc);
        }
        __syncthreads();
#pragma unroll
        for (int kk = 0; kk < 64; ++kk) {
            float a[4], w[4];
#pragma unroll
            for (int i = 0; i < 4; ++i) a[i] = Pt[tm * 4 + i][kk];
#pragma unroll
            for (int j = 0; j < 4; ++j) w[j] = Wt[tn * 4 + j][kk];
#pragma unroll
            for (int i = 0; i < 4; ++i)
#pragma unroll
                for (int j = 0; j < 4; ++j) acc[i][j] += a[i] * w[j];
        }
        __syncthreads();
    }

#pragma unroll
    for (int i = 0; i < 4; ++i) {
        const int o = tm * 4 + i;
        const float qv = q[b * COUT + o];
#pragma unroll
        for (int j = 0; j < 4; ++j) {
            const int c = c0 + tn * 4 + j;
            out[((long)b * COUT + o) * CIN + c] = acc[i][j] + qv * b2[c];
        }
    }
}

// -----------------------------------------------------------------------------
extern "C" void kernel_launch(void* const* d_in, const int* in_sizes, int n_in,
                              void* d_out, int out_size)
{
    const float* x      = (const float*)d_in[0];
    const float* w_add1 = (const float*)d_in[1];
    const float* b_add1 = (const float*)d_in[2];
    const float* w_add2 = (const float*)d_in[3];
    const float* b_add2 = (const float*)d_in[4];
    const float* w_occ1 = (const float*)d_in[5];
    const float* b_occ1 = (const float*)d_in[6];
    const float* w_occ2 = (const float*)d_in[7];
    const float* b_occ2 = (const float*)d_in[8];
    const float* w_occ3 = (const float*)d_in[9];
    float* out = (float*)d_out;

    __half *xh, *wch, *w2h, *w3h, *y1, *h1, *occ;
    float *P, *q, *bc;
    cudaGetSymbolAddress((void**)&xh,  g_xh);
    cudaGetSymbolAddress((void**)&y1,  g_y1);
    cudaGetSymbolAddress((void**)&h1,  g_h1);
    cudaGetSymbolAddress((void**)&occ, g_occ);
    cudaGetSymbolAddress((void**)&P,   g_P);
    cudaGetSymbolAddress((void**)&q,   g_q);
    cudaGetSymbolAddress((void**)&wch, g_wch);
    cudaGetSymbolAddress((void**)&w2h, g_w2h);
    cudaGetSymbolAddress((void**)&w3h, g_w3h);
    cudaGetSymbolAddress((void**)&bc,  g_bc);

    cudaFuncSetAttribute(hmma_gemm,   cudaFuncAttributeMaxDynamicSharedMemorySize, HSMEM);
    cudaFuncSetAttribute(occ_tail_tc, cudaFuncAttributeMaxDynamicSharedMemorySize, TSM);

    // launches #1-#3 (pre), #4 = hmma_gemm (ncu captures launch #4)
    xcast<<<(int)(((size_t)NB * CIN * SS) / (256 * 8)), 256>>>(x, xh);
    wsplit_all<<<(MTOT*CIN + 255) / 256, 256>>>(w_add1, w_occ1, wch);
    prep<<<(NB*COUT*CIN + 255) / 256, 256>>>(b_add1, b_occ1, w_occ2, w_occ3,
                                             bc, P, q, w2h, w3h);

    // merged add1 + occ1, all-cp.async fp16 operands
    hmma_gemm<<<dim3(SS/128, MTOT/128, NB), 128, HSMEM>>>(wch, xh, bc, y1, h1);

    // tensor-core occ tail (occ2 + occ3 + q)
    occ_tail_tc<<<dim3(SS/128, 1, NB), 128, TSM>>>(h1, w2h, b_occ2, w3h, occ, q);

    // P = (1/S) occ . y1^T  (tensor cores, fp16 in / fp32 accum)
    pool_tc<<<dim3(CIN/64, 1, NB * PSPLIT), 128>>>(occ, y1, P);

    // out = P . W2^T + q b2^T
    fin_gemm<<<dim3(CIN/64, 1, NB), 256>>>(P, q, w_add2, b_add2, out);
}